// round 10
// baseline (speedup 1.0000x reference)
#include <cuda_runtime.h>
#include <cuda_bf16.h>
#include <cstdint>
#include <cstddef>

// Problem constants: B=2, S=2048, D_MODEL=1024, H=16, d_k=64
#define BATCH 2
#define SEQ 2048
#define DM 1024
#define NH 16
#define MROWS (BATCH * SEQ)   // 4096

// ---------------------------------------------------------------------------
// bf16 pool (element offsets)
// ---------------------------------------------------------------------------
#define SZ_ACT (4096ull * 1024ull)
#define SZ_W   (1024ull * 1024ull)
#define OFF_XQ_HI 0ull
#define OFF_XQ_LO (OFF_XQ_HI + SZ_ACT)
#define OFF_XK_HI (OFF_XQ_LO + SZ_ACT)
#define OFF_XK_LO (OFF_XK_HI + SZ_ACT)
#define OFF_XV_HI (OFF_XK_LO + SZ_ACT)
#define OFF_XV_LO (OFF_XV_HI + SZ_ACT)
#define OFF_WQ_HI (OFF_XV_LO + SZ_ACT)
#define OFF_WQ_LO (OFF_WQ_HI + SZ_W)
#define OFF_WK_HI (OFF_WQ_LO + SZ_W)
#define OFF_WK_LO (OFF_WK_HI + SZ_W)
#define OFF_WV_HI (OFF_WK_LO + SZ_W)
#define OFF_WV_LO (OFF_WV_HI + SZ_W)
#define OFF_WO_HI (OFF_WV_LO + SZ_W)
#define OFF_WO_LO (OFF_WO_HI + SZ_W)
#define OFF_CTX_HI (OFF_WO_LO + SZ_W)
#define OFF_CTX_LO (OFF_CTX_HI + SZ_ACT)
// head-major attention operands: [b*16+h][s][64]
#define OFF_AQ_HI (OFF_CTX_LO + SZ_ACT)
#define OFF_AQ_LO (OFF_AQ_HI + SZ_ACT)
#define OFF_AK_HI (OFF_AQ_LO + SZ_ACT)
#define OFF_AK_LO (OFF_AK_HI + SZ_ACT)
#define OFF_AV_HI (OFF_AK_LO + SZ_ACT)
#define OFF_AV_LO (OFF_AV_HI + SZ_ACT)
#define BF_TOTAL  (OFF_AV_LO + SZ_ACT)
__device__ __nv_bfloat16 g_bf[BF_TOTAL];

// ---------------------------------------------------------------------------
// PTX helpers — baseline ISA only (cp.async / ldmatrix / mma.sync / cvt)
// ---------------------------------------------------------------------------
__device__ __forceinline__ uint32_t smem_u32(const void* p) {
    uint32_t a;
    asm("{ .reg .u64 t; cvta.to.shared.u64 t, %1; cvt.u32.u64 %0, t; }"
        : "=r"(a) : "l"(p));
    return a;
}

#define CP_ASYNC16(dst, src) \
    asm volatile("cp.async.cg.shared.global [%0], [%1], 16;" :: "r"(dst), "l"(src))
#define CP_COMMIT() asm volatile("cp.async.commit_group;" ::: "memory")
#define CP_WAIT(N)  asm volatile("cp.async.wait_group %0;" :: "n"(N) : "memory")

#define LDSM4(R, addr) \
    asm volatile("ldmatrix.sync.aligned.m8n8.x4.shared.b16 {%0,%1,%2,%3}, [%4];" \
        : "=r"((R)[0]), "=r"((R)[1]), "=r"((R)[2]), "=r"((R)[3]) : "r"(addr))
#define LDSM4T(R, addr) \
    asm volatile("ldmatrix.sync.aligned.m8n8.x4.trans.shared.b16 {%0,%1,%2,%3}, [%4];" \
        : "=r"((R)[0]), "=r"((R)[1]), "=r"((R)[2]), "=r"((R)[3]) : "r"(addr))

#define MMA16816(C, A, b0, b1) \
    asm volatile("mma.sync.aligned.m16n8k16.row.col.f32.bf16.bf16.f32 " \
        "{%0,%1,%2,%3}, {%4,%5,%6,%7}, {%8,%9}, {%0,%1,%2,%3};" \
        : "+f"((C)[0]), "+f"((C)[1]), "+f"((C)[2]), "+f"((C)[3]) \
        : "r"((A)[0]), "r"((A)[1]), "r"((A)[2]), "r"((A)[3]), "r"(b0), "r"(b1))

__device__ __forceinline__ float ex2(float x) {
    float r; asm("ex2.approx.ftz.f32 %0, %1;" : "=f"(r) : "f"(x)); return r;
}
__device__ __forceinline__ uint32_t packbf(float lo, float hi) {
    uint32_t u;
    asm("cvt.rn.bf16x2.f32 %0, %1, %2;" : "=r"(u) : "f"(hi), "f"(lo));
    return u;
}
__device__ __forceinline__ float bflo(uint32_t u) { return __uint_as_float(u << 16); }
__device__ __forceinline__ float bfhi(uint32_t u) { return __uint_as_float(u & 0xffff0000u); }

__device__ __forceinline__ void split_store2(
    __nv_bfloat16* hp, __nv_bfloat16* lp, size_t idx, float a, float b)
{
    __nv_bfloat16 ha = __float2bfloat16(a);
    __nv_bfloat16 hb = __float2bfloat16(b);
    __nv_bfloat16 la = __float2bfloat16(a - __bfloat162float(ha));
    __nv_bfloat16 lb = __float2bfloat16(b - __bfloat162float(hb));
    *reinterpret_cast<__nv_bfloat162*>(hp + idx) = __nv_bfloat162(ha, hb);
    *reinterpret_cast<__nv_bfloat162*>(lp + idx) = __nv_bfloat162(la, lb);
}

// ---------------------------------------------------------------------------
// ONE merged fp32 -> bf16 hi/lo split conversion for all 7 tensors.
// ---------------------------------------------------------------------------
__global__ __launch_bounds__(256) void convert_all(
    const float* __restrict__ q, const float* __restrict__ k,
    const float* __restrict__ v, const float* __restrict__ wq,
    const float* __restrict__ wk, const float* __restrict__ wv,
    const float* __restrict__ wo)
{
    const int blk = blockIdx.x;
    const float* src;
    size_t hiOff, loOff, base;
    if (blk < 12288) {
        int t = blk >> 12;
        src = (t == 0) ? q : (t == 1) ? k : v;
        hiOff = (t == 0) ? OFF_XQ_HI : (t == 1) ? OFF_XK_HI : OFF_XV_HI;
        loOff = (t == 0) ? OFF_XQ_LO : (t == 1) ? OFF_XK_LO : OFF_XV_LO;
        base = ((size_t)(blk & 4095)) << 10;
    } else {
        int t = (blk - 12288) >> 10;
        src = (t == 0) ? wq : (t == 1) ? wk : (t == 2) ? wv : wo;
        hiOff = (t == 0) ? OFF_WQ_HI : (t == 1) ? OFF_WK_HI
              : (t == 2) ? OFF_WV_HI : OFF_WO_HI;
        loOff = (t == 0) ? OFF_WQ_LO : (t == 1) ? OFF_WK_LO
              : (t == 2) ? OFF_WV_LO : OFF_WO_LO;
        base = ((size_t)((blk - 12288) & 1023)) << 10;
    }
    size_t i = base + (size_t)threadIdx.x * 4;
    float4 x = *(const float4*)(src + i);
    __nv_bfloat16 h[4], l[4];
    float vv[4] = {x.x, x.y, x.z, x.w};
#pragma unroll
    for (int j = 0; j < 4; j++) {
        h[j] = __float2bfloat16(vv[j]);
        l[j] = __float2bfloat16(vv[j] - __bfloat162float(h[j]));
    }
    *reinterpret_cast<__nv_bfloat162*>(g_bf + hiOff + i)     = __nv_bfloat162(h[0], h[1]);
    *reinterpret_cast<__nv_bfloat162*>(g_bf + hiOff + i + 2) = __nv_bfloat162(h[2], h[3]);
    *reinterpret_cast<__nv_bfloat162*>(g_bf + loOff + i)     = __nv_bfloat162(l[0], l[1]);
    *reinterpret_cast<__nv_bfloat162*>(g_bf + loOff + i + 2) = __nv_bfloat162(l[2], l[3]);
}

// ---------------------------------------------------------------------------
// GEMM core: 256 threads, 2x4 warp grid, 64x32 warp tiles, CTA tile 128x128.
// 4-stage cp.async pipeline, ONE barrier per k-tile (multistage pattern):
// the barrier at iter kt proves all warps finished reading stage (kt-1)%4,
// which is exactly the stage the subsequent issue(kt+3) overwrites.
// ---------------------------------------------------------------------------
#define NT 32
#define KT 32
#define ROWB 80
#define TILEB (128 * ROWB)
#define STAGEB (4 * TILEB)
#define GNSTG 4
#define GEMM_SMEM (GNSTG * STAGEB)   // 163840 B

struct GemmAcc { float a[4][4][4]; };

__device__ __forceinline__ void gemm_core(
    uint32_t sbase, size_t aHi, size_t aLo, size_t bHi, size_t bLo,
    int m0, int n0, GemmAcc& A)
{
    const int tid  = threadIdx.x;
    const int lane = tid & 31;
    const int wid  = tid >> 5;

    const __nv_bfloat16* gp0 = g_bf + aHi + (size_t)m0 * 1024;
    const __nv_bfloat16* gp1 = g_bf + aLo + (size_t)m0 * 1024;
    const __nv_bfloat16* gp2 = g_bf + bHi + (size_t)n0 * 1024;
    const __nv_bfloat16* gp3 = g_bf + bLo + (size_t)n0 * 1024;

    auto issue = [&](int kt, int stage) {
        const int kc = kt * KT;
#pragma unroll
        for (int j = 0; j < 8; j++) {
            int c    = tid + j * 256;
            int tile = c >> 9;
            int r    = (c >> 2) & 127;
            int qq   = c & 3;
            uint32_t dst = sbase + stage * STAGEB + tile * TILEB + r * ROWB + qq * 16;
            const __nv_bfloat16* base =
                (tile == 0) ? gp0 : (tile == 1) ? gp1 : (tile == 2) ? gp2 : gp3;
            CP_ASYNC16(dst, base + (size_t)r * 1024 + kc + qq * 8);
        }
        CP_COMMIT();
    };

    issue(0, 0);
    issue(1, 1);
    issue(2, 2);

    const int wm = wid & 1;
    const int wn = wid >> 1;
    const int a_row  = (lane & 7) + ((lane >> 3) & 1) * 8;
    const int a_colb = ((lane >> 4) * 8) * 2;
    const int b_row  = (lane & 7) + ((lane >> 4)) * 8;
    const int b_colb = (((lane >> 3) & 1) * 8) * 2;

#pragma unroll
    for (int i = 0; i < 4; i++)
#pragma unroll
        for (int j = 0; j < 4; j++)
#pragma unroll
            for (int e = 0; e < 4; e++) A.a[i][j][e] = 0.f;

    for (int kt = 0; kt < NT; kt++) {
        // group kt must be complete: pending may be kt+1, kt+2
        if (kt < 30) CP_WAIT(2);
        else if (kt == 30) CP_WAIT(1);
        else CP_WAIT(0);
        __syncthreads();   // all warps done reading stage (kt-1)%4

        if (kt + 3 < NT) issue(kt + 3, (kt + 3) & 3);

        const uint32_t st = sbase + (kt & 3) * STAGEB;

#pragma unroll
        for (int ks = 0; ks < 2; ks++) {
            uint32_t aH[4][4], aL[4][4];
#pragma unroll
            for (int i = 0; i < 4; i++) {
                uint32_t ad = st + (wm * 64 + i * 16 + a_row) * ROWB + ks * 32 + a_colb;
                LDSM4(aH[i], ad);
                LDSM4(aL[i], ad + TILEB);
            }
            uint32_t bH[2][4], bL[2][4];
#pragma unroll
            for (int j = 0; j < 2; j++) {
                uint32_t bd = st + 2 * TILEB +
                              (wn * 32 + j * 16 + b_row) * ROWB + ks * 32 + b_colb;
                LDSM4(bH[j], bd);
                LDSM4(bL[j], bd + TILEB);
            }
#pragma unroll
            for (int i = 0; i < 4; i++) {
#pragma unroll
                for (int jf = 0; jf < 4; jf++) {
                    uint32_t h0 = bH[jf >> 1][(jf & 1) * 2];
                    uint32_t h1 = bH[jf >> 1][(jf & 1) * 2 + 1];
                    uint32_t l0 = bL[jf >> 1][(jf & 1) * 2];
                    uint32_t l1 = bL[jf >> 1][(jf & 1) * 2 + 1];
                    MMA16816(A.a[i][jf], aH[i], h0, h1);
                    MMA16816(A.a[i][jf], aH[i], l0, l1);
                    MMA16816(A.a[i][jf], aL[i], h0, h1);
                }
            }
        }
        // no trailing barrier — next iteration's top barrier provides safety
    }
}

// QKV projections merged into one launch: blockIdx.z in {0,1,2}
__global__ __launch_bounds__(256) void gemm_qkv(
    const float* __restrict__ bq, const float* __restrict__ bk,
    const float* __restrict__ bv)
{
    extern __shared__ char sm[];
    const uint32_t sbase = smem_u32(sm);
    const int lane = threadIdx.x & 31;
    const int wid  = threadIdx.x >> 5;
    const int m0 = blockIdx.y << 7;
    const int n0 = blockIdx.x << 7;
    const int z  = blockIdx.z;

    size_t aHi, aLo, bHi, bLo, dH, dL;
    const float* bias;
    if (z == 0) { aHi = OFF_XQ_HI; aLo = OFF_XQ_LO; bHi = OFF_WQ_HI; bLo = OFF_WQ_LO;
                  dH = OFF_AQ_HI; dL = OFF_AQ_LO; bias = bq; }
    else if (z == 1) { aHi = OFF_XK_HI; aLo = OFF_XK_LO; bHi = OFF_WK_HI; bLo = OFF_WK_LO;
                  dH = OFF_AK_HI; dL = OFF_AK_LO; bias = bk; }
    else { aHi = OFF_XV_HI; aLo = OFF_XV_LO; bHi = OFF_WV_HI; bLo = OFF_WV_LO;
                  dH = OFF_AV_HI; dL = OFF_AV_LO; bias = bv; }

    GemmAcc A;
    gemm_core(sbase, aHi, aLo, bHi, bLo, m0, n0, A);

    const int mrb = m0 + (wid & 1) * 64;
    const int ncb = n0 + (wid >> 1) * 32;
    __nv_bfloat16* hp = g_bf + dH;
    __nv_bfloat16* lp = g_bf + dL;
#pragma unroll
    for (int i = 0; i < 4; i++) {
        int r0 = mrb + i * 16 + (lane >> 2);
#pragma unroll
        for (int jf = 0; jf < 4; jf++) {
            int c = ncb + jf * 8 + (lane & 3) * 2;
            float bx = __ldg(bias + c);
            float by = __ldg(bias + c + 1);
            int h = c >> 6, d = c & 63;
            size_t ix0 = ((size_t)(((r0 >> 11) << 4) | h) << 17)
                       + ((size_t)(r0 & 2047) << 6) + d;
            split_store2(hp, lp, ix0, A.a[i][jf][0] + bx, A.a[i][jf][1] + by);
            split_store2(hp, lp, ix0 + (8ull << 6), A.a[i][jf][2] + bx, A.a[i][jf][3] + by);
        }
    }
}

// Output projection: ctx (split bf16) x Wo^T + bo -> fp32 out
__global__ __launch_bounds__(256) void gemm_out(
    const float* __restrict__ bias, float* __restrict__ ext)
{
    extern __shared__ char sm[];
    const uint32_t sbase = smem_u32(sm);
    const int lane = threadIdx.x & 31;
    const int wid  = threadIdx.x >> 5;
    const int m0 = blockIdx.y << 7;
    const int n0 = blockIdx.x << 7;

    GemmAcc A;
    gemm_core(sbase, OFF_CTX_HI, OFF_CTX_LO, OFF_WO_HI, OFF_WO_LO, m0, n0, A);

    const int mrb = m0 + (wid & 1) * 64;
    const int ncb = n0 + (wid >> 1) * 32;
#pragma unroll
    for (int i = 0; i < 4; i++) {
        int r0 = mrb + i * 16 + (lane >> 2);
#pragma unroll
        for (int jf = 0; jf < 4; jf++) {
            int cb = ncb + jf * 8 + (lane & 3) * 2;
            float bx = __ldg(bias + cb);
            float by = __ldg(bias + cb + 1);
            float2 o0 = make_float2(A.a[i][jf][0] + bx, A.a[i][jf][1] + by);
            float2 o1 = make_float2(A.a[i][jf][2] + bx, A.a[i][jf][3] + by);
            *reinterpret_cast<float2*>(ext + (size_t)r0 * 1024 + cb)       = o0;
            *reinterpret_cast<float2*>(ext + (size_t)(r0 + 8) * 1024 + cb) = o1;
        }
    }
}

// ---------------------------------------------------------------------------
// Tensor-core flash attention (split-bf16, fixed-scale softmax).
// CTA: 128 queries x one (b,h). 8 warps x 16-q tiles. Key tiles of 64.
// 3-stage cp.async pipeline (wait ladder 2/1/0); unchanged from R8 (near floor).
// ---------------------------------------------------------------------------
#define ATT_STAGE 32768            // KH 8K | KL 8K | VH 8K | VL 8K
#define ATT_NSTG  3
#define ATT_SMEM  (ATT_NSTG * ATT_STAGE)  // 96 KB

__global__ __launch_bounds__(256, 2) void attn_tc()
{
    extern __shared__ char sm[];
    const uint32_t sb = smem_u32(sm);
    const int tid = threadIdx.x, lane = tid & 31, wid = tid >> 5;
    const int bh = blockIdx.y;
    const int q0 = blockIdx.x << 7;

    const __nv_bfloat16* Qh = g_bf + OFF_AQ_HI + ((size_t)bh << 17) + ((size_t)q0 << 6);
    const __nv_bfloat16* Ql = g_bf + OFF_AQ_LO + ((size_t)bh << 17) + ((size_t)q0 << 6);
    const __nv_bfloat16* Kh = g_bf + OFF_AK_HI + ((size_t)bh << 17);
    const __nv_bfloat16* Kl = g_bf + OFF_AK_LO + ((size_t)bh << 17);
    const __nv_bfloat16* Vh = g_bf + OFF_AV_HI + ((size_t)bh << 17);
    const __nv_bfloat16* Vl = g_bf + OFF_AV_LO + ((size_t)bh << 17);

    // ---- stage Q tile (128x64 hi+lo) into stage-0 smem, then to registers ----
#pragma unroll
    for (int j = 0; j < 8; j++) {
        int c = tid + j * 256;
        int t = c >> 10;
        int r = (c >> 3) & 127;
        int cb = c & 7;
        uint32_t dst = sb + t * 16384 + r * 128 + ((cb ^ (r & 7)) << 4);
        const __nv_bfloat16* src = (t ? Ql : Qh) + (size_t)r * 64 + cb * 8;
        CP_ASYNC16(dst, src);
    }
    CP_COMMIT(); CP_WAIT(0);
    __syncthreads();

    uint32_t aQh[4][4], aQl[4][4];
    {
        int row = (wid << 4) + (lane & 7) + ((lane >> 3) & 1) * 8;
#pragma unroll
        for (int ks = 0; ks < 4; ks++) {
            int cb = ks * 2 + (lane >> 4);
            uint32_t ad = sb + row * 128 + ((cb ^ (row & 7)) << 4);
            LDSM4(aQh[ks], ad);
            LDSM4(aQl[ks], ad + 16384);
        }
    }
    __syncthreads();

    // ---- KV pipeline ----
    auto issue = [&](int kt, int stg) {
        const int k0 = kt << 6;
#pragma unroll
        for (int j = 0; j < 8; j++) {
            int c = tid + j * 256;
            int t = c >> 9;
            int r = (c >> 3) & 63;
            int cb = c & 7;
            uint32_t dst = sb + stg * ATT_STAGE + t * 8192 + r * 128 + ((cb ^ (r & 7)) << 4);
            const __nv_bfloat16* base = (t == 0) ? Kh : (t == 1) ? Kl : (t == 2) ? Vh : Vl;
            CP_ASYNC16(dst, base + (size_t)(k0 + r) * 64 + cb * 8);
        }
        CP_COMMIT();
    };
    issue(0, 0);
    issue(1, 1);
    issue(2, 2);

    float O[8][4];
#pragma unroll
    for (int f = 0; f < 8; f++)
#pragma unroll
        for (int e = 0; e < 4; e++) O[f][e] = 0.f;
    float l0 = 0.f, l1 = 0.f;
    const float cs = 0.125f * 1.4426950408889634f;

    const int krow = (lane & 7) + (lane >> 4) * 8;
    const int kcb  = (lane >> 3) & 1;
    const int vrow = (lane & 7) + ((lane >> 3) & 1) * 8;
    const int vcb  = lane >> 4;

    int stg = 0;  // kt % 3
    for (int kt = 0; kt < 32; kt++) {
        if (kt < 30) CP_WAIT(2);
        else if (kt == 30) CP_WAIT(1);
        else CP_WAIT(0);
        __syncthreads();
        const uint32_t st = sb + stg * ATT_STAGE;

        // two key-halves of 32 keys each: compute S-half, softmax, PV-half
#pragma unroll
        for (int h2 = 0; h2 < 2; h2++) {
            float S[4][4];
#pragma unroll
            for (int f = 0; f < 4; f++)
#pragma unroll
                for (int e = 0; e < 4; e++) S[f][e] = 0.f;

#pragma unroll
            for (int ks = 0; ks < 4; ks++) {
#pragma unroll
                for (int gg = 0; gg < 2; gg++) {
                    int g = 2 * h2 + gg;
                    int rr = g * 16 + krow;
                    int cb = ks * 2 + kcb;
                    uint32_t ad = st + rr * 128 + ((cb ^ (rr & 7)) << 4);
                    uint32_t KH[4], KL[4];
                    LDSM4(KH, ad);
                    LDSM4(KL, ad + 8192);
                    MMA16816(S[2 * gg],     aQh[ks], KH[0], KH[1]);
                    MMA16816(S[2 * gg],     aQh[ks], KL[0], KL[1]);
                    MMA16816(S[2 * gg],     aQl[ks], KH[0], KH[1]);
                    MMA16816(S[2 * gg + 1], aQh[ks], KH[2], KH[3]);
                    MMA16816(S[2 * gg + 1], aQh[ks], KL[2], KL[3]);
                    MMA16816(S[2 * gg + 1], aQl[ks], KH[2], KH[3]);
                }
            }

#pragma unroll
            for (int f = 0; f < 4; f++) {
#pragma unroll
                for (int e = 0; e < 4; e++) S[f][e] = ex2(S[f][e] * cs);
                l0 += S[f][0] + S[f][1];
                l1 += S[f][2] + S[f][3];
            }

#pragma unroll
            for (int jj = 0; jj < 2; jj++) {
                int kk = 2 * h2 + jj;
                uint32_t pH[4], pL[4];
                float* Sa = S[2 * jj];
                float* Sb = S[2 * jj + 1];
                pH[0] = packbf(Sa[0], Sa[1]);
                pH[1] = packbf(Sa[2], Sa[3]);
                pH[2] = packbf(Sb[0], Sb[1]);
                pH[3] = packbf(Sb[2], Sb[3]);
                pL[0] = packbf(Sa[0] - bflo(pH[0]), Sa[1] - bfhi(pH[0]));
                pL[1] = packbf(Sa[2] - bflo(pH[1]), Sa[3] - bfhi(pH[1]));
                pL[2] = packbf(Sb[0] - bflo(pH[2]), Sb[1] - bfhi(pH[2]));
                pL[3] = packbf(Sb[2] - bflo(pH[3]), Sb[3] - bfhi(pH[3]));
#pragma unroll
                for (int dp = 0; dp < 4; dp++) {
                    int rr = kk * 16 + vrow;
                    int cb = dp * 2 + vcb;
                    uint32_t ad = st + 16384 + rr * 128 + ((cb ^ (rr & 7)) << 4);
                    uint32_t VH[4], VL[4];
                    LDSM4T(VH, ad);
                    LDSM4T(VL, ad + 8192);
                    MMA16816(O[2 * dp],     pH, VH[0], VH[1]);
                    MMA16816(O[2 * dp],     pH, VL[0], VL[1]);
                    MMA16816(O[2 * dp],     pL, VH[0], VH[1]);
                    MMA16816(O[2 * dp + 1], pH, VH[2], VH[3]);
                    MMA16816(O[2 * dp + 1], pH, VL[2], VL[3]);
                    MMA16816(O[2 * dp + 1], pL, VH[2], VH[3]);
                }
            }
        }

        __syncthreads();
        if (kt + 3 < 32) issue(kt + 3, stg);   // tile kt+3 reuses stage kt%3
        stg = (stg == 2) ? 0 : stg + 1;
    }

    // ---- epilogue: normalize and write ctx as bf16 hi/lo [b,s,1024] ----
    l0 += __shfl_xor_sync(0xffffffffu, l0, 1);
    l0 += __shfl_xor_sync(0xffffffffu, l0, 2);
    l1 += __shfl_xor_sync(0xffffffffu, l1, 1);
    l1 += __shfl_xor_sync(0xffffffffu, l1, 2);
    const float inv0 = 1.f / l0;
    const float inv1 = 1.f / l1;

    const int b = bh >> 4, h = bh & 15;
    const int r0g = b * 2048 + q0 + (wid << 4) + (lane >> 2);
    __nv_bfloat16* ch = g_bf + OFF_CTX_HI;
    __nv_bfloat16* cl = g_bf + OFF_CTX_LO;
#pragma unroll
    for (int f = 0; f < 8; f++) {
        int col = (h << 6) + f * 8 + (lane & 3) * 2;
        split_store2(ch, cl, (size_t)r0g * 1024 + col,
                     O[f][0] * inv0, O[f][1] * inv0);
        split_store2(ch, cl, (size_t)(r0g + 8) * 1024 + col,
                     O[f][2] * inv1, O[f][3] * inv1);
    }
}

// ---------------------------------------------------------------------------
extern "C" void kernel_launch(void* const* d_in, const int* in_sizes, int n_in,
                              void* d_out, int out_size)
{
    const float* query = (const float*)d_in[0];
    const float* key   = (const float*)d_in[1];
    const float* value = (const float*)d_in[2];
    const float* Wq = (const float*)d_in[3];
    const float* bq = (const float*)d_in[4];
    const float* Wk = (const float*)d_in[5];
    const float* bk = (const float*)d_in[6];
    const float* Wv = (const float*)d_in[7];
    const float* bv = (const float*)d_in[8];
    const float* Wo = (const float*)d_in[9];
    const float* bo = (const float*)d_in[10];
    float* out = (float*)d_out;

    cudaFuncSetAttribute(gemm_qkv, cudaFuncAttributeMaxDynamicSharedMemorySize, GEMM_SMEM);
    cudaFuncSetAttribute(gemm_out, cudaFuncAttributeMaxDynamicSharedMemorySize, GEMM_SMEM);
    cudaFuncSetAttribute(attn_tc,  cudaFuncAttributeMaxDynamicSharedMemorySize, ATT_SMEM);

    convert_all<<<16384, 256>>>(query, key, value, Wq, Wk, Wv, Wo);

    gemm_qkv<<<dim3(DM / 128, MROWS / 128, 3), 256, GEMM_SMEM>>>(bq, bk, bv);

    attn_tc<<<dim3(SEQ / 128, BATCH * NH), 256, ATT_SMEM>>>();

    gemm_out<<<dim3(DM / 128, MROWS / 128), 256, GEMM_SMEM>>>(bo, out);
}

// round 11
// speedup vs baseline: 1.0325x; 1.0325x over previous
#include <cuda_runtime.h>
#include <cuda_bf16.h>
#include <cstdint>
#include <cstddef>

// Problem constants: B=2, S=2048, D_MODEL=1024, H=16, d_k=64
#define BATCH 2
#define SEQ 2048
#define DM 1024
#define NH 16
#define MROWS (BATCH * SEQ)   // 4096

// ---------------------------------------------------------------------------
// bf16 pool (element offsets)
// ---------------------------------------------------------------------------
#define SZ_ACT (4096ull * 1024ull)
#define SZ_W   (1024ull * 1024ull)
#define OFF_XQ_HI 0ull
#define OFF_XQ_LO (OFF_XQ_HI + SZ_ACT)
#define OFF_XK_HI (OFF_XQ_LO + SZ_ACT)
#define OFF_XK_LO (OFF_XK_HI + SZ_ACT)
#define OFF_XV_HI (OFF_XK_LO + SZ_ACT)
#define OFF_XV_LO (OFF_XV_HI + SZ_ACT)
#define OFF_WQ_HI (OFF_XV_LO + SZ_ACT)
#define OFF_WQ_LO (OFF_WQ_HI + SZ_W)
#define OFF_WK_HI (OFF_WQ_LO + SZ_W)
#define OFF_WK_LO (OFF_WK_HI + SZ_W)
#define OFF_WV_HI (OFF_WK_LO + SZ_W)
#define OFF_WV_LO (OFF_WV_HI + SZ_W)
#define OFF_WO_HI (OFF_WV_LO + SZ_W)
#define OFF_WO_LO (OFF_WO_HI + SZ_W)
#define OFF_CTX_HI (OFF_WO_LO + SZ_W)
#define OFF_CTX_LO (OFF_CTX_HI + SZ_ACT)
// head-major attention operands: [b*16+h][s][64]
#define OFF_AQ_HI (OFF_CTX_LO + SZ_ACT)
#define OFF_AQ_LO (OFF_AQ_HI + SZ_ACT)
#define OFF_AK_HI (OFF_AQ_LO + SZ_ACT)
#define OFF_AK_LO (OFF_AK_HI + SZ_ACT)
#define OFF_AV_HI (OFF_AK_LO + SZ_ACT)
#define OFF_AV_LO (OFF_AV_HI + SZ_ACT)
#define BF_TOTAL  (OFF_AV_LO + SZ_ACT)
__device__ __nv_bfloat16 g_bf[BF_TOTAL];

// ---------------------------------------------------------------------------
// PTX helpers — baseline ISA only (cp.async / ldmatrix / mma.sync / cvt)
// ---------------------------------------------------------------------------
__device__ __forceinline__ uint32_t smem_u32(const void* p) {
    uint32_t a;
    asm("{ .reg .u64 t; cvta.to.shared.u64 t, %1; cvt.u32.u64 %0, t; }"
        : "=r"(a) : "l"(p));
    return a;
}

#define CP_ASYNC16(dst, src) \
    asm volatile("cp.async.cg.shared.global [%0], [%1], 16;" :: "r"(dst), "l"(src))
#define CP_COMMIT() asm volatile("cp.async.commit_group;" ::: "memory")
#define CP_WAIT(N)  asm volatile("cp.async.wait_group %0;" :: "n"(N) : "memory")

#define LDSM4(R, addr) \
    asm volatile("ldmatrix.sync.aligned.m8n8.x4.shared.b16 {%0,%1,%2,%3}, [%4];" \
        : "=r"((R)[0]), "=r"((R)[1]), "=r"((R)[2]), "=r"((R)[3]) : "r"(addr))
#define LDSM4T(R, addr) \
    asm volatile("ldmatrix.sync.aligned.m8n8.x4.trans.shared.b16 {%0,%1,%2,%3}, [%4];" \
        : "=r"((R)[0]), "=r"((R)[1]), "=r"((R)[2]), "=r"((R)[3]) : "r"(addr))

#define MMA16816(C, A, b0, b1) \
    asm volatile("mma.sync.aligned.m16n8k16.row.col.f32.bf16.bf16.f32 " \
        "{%0,%1,%2,%3}, {%4,%5,%6,%7}, {%8,%9}, {%0,%1,%2,%3};" \
        : "+f"((C)[0]), "+f"((C)[1]), "+f"((C)[2]), "+f"((C)[3]) \
        : "r"((A)[0]), "r"((A)[1]), "r"((A)[2]), "r"((A)[3]), "r"(b0), "r"(b1))

__device__ __forceinline__ float ex2(float x) {
    float r; asm("ex2.approx.ftz.f32 %0, %1;" : "=f"(r) : "f"(x)); return r;
}
__device__ __forceinline__ uint32_t packbf(float lo, float hi) {
    uint32_t u;
    asm("cvt.rn.bf16x2.f32 %0, %1, %2;" : "=r"(u) : "f"(hi), "f"(lo));
    return u;
}
__device__ __forceinline__ float bflo(uint32_t u) { return __uint_as_float(u << 16); }
__device__ __forceinline__ float bfhi(uint32_t u) { return __uint_as_float(u & 0xffff0000u); }

__device__ __forceinline__ void split_store2(
    __nv_bfloat16* hp, __nv_bfloat16* lp, size_t idx, float a, float b)
{
    __nv_bfloat16 ha = __float2bfloat16(a);
    __nv_bfloat16 hb = __float2bfloat16(b);
    __nv_bfloat16 la = __float2bfloat16(a - __bfloat162float(ha));
    __nv_bfloat16 lb = __float2bfloat16(b - __bfloat162float(hb));
    *reinterpret_cast<__nv_bfloat162*>(hp + idx) = __nv_bfloat162(ha, hb);
    *reinterpret_cast<__nv_bfloat162*>(lp + idx) = __nv_bfloat162(la, lb);
}

// ---------------------------------------------------------------------------
// ONE merged fp32 -> bf16 hi/lo split conversion for all 7 tensors.
// ---------------------------------------------------------------------------
__global__ __launch_bounds__(256) void convert_all(
    const float* __restrict__ q, const float* __restrict__ k,
    const float* __restrict__ v, const float* __restrict__ wq,
    const float* __restrict__ wk, const float* __restrict__ wv,
    const float* __restrict__ wo)
{
    const int blk = blockIdx.x;
    const float* src;
    size_t hiOff, loOff, base;
    if (blk < 12288) {
        int t = blk >> 12;
        src = (t == 0) ? q : (t == 1) ? k : v;
        hiOff = (t == 0) ? OFF_XQ_HI : (t == 1) ? OFF_XK_HI : OFF_XV_HI;
        loOff = (t == 0) ? OFF_XQ_LO : (t == 1) ? OFF_XK_LO : OFF_XV_LO;
        base = ((size_t)(blk & 4095)) << 10;
    } else {
        int t = (blk - 12288) >> 10;
        src = (t == 0) ? wq : (t == 1) ? wk : (t == 2) ? wv : wo;
        hiOff = (t == 0) ? OFF_WQ_HI : (t == 1) ? OFF_WK_HI
              : (t == 2) ? OFF_WV_HI : OFF_WO_HI;
        loOff = (t == 0) ? OFF_WQ_LO : (t == 1) ? OFF_WK_LO
              : (t == 2) ? OFF_WV_LO : OFF_WO_LO;
        base = ((size_t)((blk - 12288) & 1023)) << 10;
    }
    size_t i = base + (size_t)threadIdx.x * 4;
    float4 x = *(const float4*)(src + i);
    __nv_bfloat16 h[4], l[4];
    float vv[4] = {x.x, x.y, x.z, x.w};
#pragma unroll
    for (int j = 0; j < 4; j++) {
        h[j] = __float2bfloat16(vv[j]);
        l[j] = __float2bfloat16(vv[j] - __bfloat162float(h[j]));
    }
    *reinterpret_cast<__nv_bfloat162*>(g_bf + hiOff + i)     = __nv_bfloat162(h[0], h[1]);
    *reinterpret_cast<__nv_bfloat162*>(g_bf + hiOff + i + 2) = __nv_bfloat162(h[2], h[3]);
    *reinterpret_cast<__nv_bfloat162*>(g_bf + loOff + i)     = __nv_bfloat162(l[0], l[1]);
    *reinterpret_cast<__nv_bfloat162*>(g_bf + loOff + i + 2) = __nv_bfloat162(l[2], l[3]);
}

// ---------------------------------------------------------------------------
// GEMM core: CTA tile 128x64, 256 threads, warp grid 2(M)x4(N),
// warp tile 64x16. 2-stage cp.async pipeline (R8-proven structure).
// Low register footprint (~90) -> 2 CTAs/SM -> 4 warps/SMSP.
// ---------------------------------------------------------------------------
#define NT 32
#define KT 32
#define ROWB 80
#define AT_BYTES (128 * ROWB)        // 10240 per A tile (hi or lo)
#define BT_BYTES (64 * ROWB)         // 5120 per B tile
#define STAGEB (2 * AT_BYTES + 2 * BT_BYTES)  // 30720
#define GEMM_SMEM (2 * STAGEB)       // 61440

struct GemmAcc { float a[4][2][4]; };

__device__ __forceinline__ void gemm_core(
    uint32_t sbase, size_t aHi, size_t aLo, size_t bHi, size_t bLo,
    int m0, int n0, GemmAcc& A)
{
    const int tid  = threadIdx.x;
    const int lane = tid & 31;
    const int wid  = tid >> 5;

    const __nv_bfloat16* gp0 = g_bf + aHi + (size_t)m0 * 1024;
    const __nv_bfloat16* gp1 = g_bf + aLo + (size_t)m0 * 1024;
    const __nv_bfloat16* gp2 = g_bf + bHi + (size_t)n0 * 1024;
    const __nv_bfloat16* gp3 = g_bf + bLo + (size_t)n0 * 1024;

    // 1536 16B chunks per stage (A 1024, B 512) -> 6 per thread
    auto issue = [&](int kt, int stage) {
        const int kc = kt * KT;
#pragma unroll
        for (int j = 0; j < 6; j++) {
            int c = tid + j * 256;
            uint32_t dst;
            const __nv_bfloat16* src;
            if (c < 1024) {
                int tile = c >> 9;            // 0 Ahi, 1 Alo
                int r    = (c >> 2) & 127;
                int qq   = c & 3;
                dst = sbase + stage * STAGEB + tile * AT_BYTES + r * ROWB + qq * 16;
                src = (tile ? gp1 : gp0) + (size_t)r * 1024 + kc + qq * 8;
            } else {
                int c2   = c - 1024;
                int tile = c2 >> 8;           // 0 Bhi, 1 Blo
                int r    = (c2 >> 2) & 63;
                int qq   = c2 & 3;
                dst = sbase + stage * STAGEB + 2 * AT_BYTES + tile * BT_BYTES
                    + r * ROWB + qq * 16;
                src = (tile ? gp3 : gp2) + (size_t)r * 1024 + kc + qq * 8;
            }
            CP_ASYNC16(dst, src);
        }
        CP_COMMIT();
    };

    issue(0, 0);
    issue(1, 1);

    const int wm = wid & 1;      // 2 M groups of 64
    const int wn = wid >> 1;     // 4 N groups of 16
    const int a_row  = (lane & 7) + ((lane >> 3) & 1) * 8;
    const int a_colb = ((lane >> 4) * 8) * 2;
    const int b_row  = (lane & 7) + ((lane >> 4)) * 8;
    const int b_colb = (((lane >> 3) & 1) * 8) * 2;

#pragma unroll
    for (int i = 0; i < 4; i++)
#pragma unroll
        for (int j = 0; j < 2; j++)
#pragma unroll
            for (int e = 0; e < 4; e++) A.a[i][j][e] = 0.f;

    for (int kt = 0; kt < NT; kt++) {
        if (kt == NT - 1) CP_WAIT(0); else CP_WAIT(1);
        __syncthreads();
        const uint32_t st = sbase + (kt & 1) * STAGEB;

#pragma unroll
        for (int ks = 0; ks < 2; ks++) {
            uint32_t aH[4][4], aL[4][4];
#pragma unroll
            for (int i = 0; i < 4; i++) {
                uint32_t ad = st + (wm * 64 + i * 16 + a_row) * ROWB + ks * 32 + a_colb;
                LDSM4(aH[i], ad);
                LDSM4(aL[i], ad + AT_BYTES);
            }
            uint32_t bH[4], bL[4];
            {
                uint32_t bd = st + 2 * AT_BYTES +
                              (wn * 16 + b_row) * ROWB + ks * 32 + b_colb;
                LDSM4(bH, bd);
                LDSM4(bL, bd + BT_BYTES);
            }
#pragma unroll
            for (int i = 0; i < 4; i++) {
#pragma unroll
                for (int jf = 0; jf < 2; jf++) {
                    uint32_t h0 = bH[jf * 2], h1 = bH[jf * 2 + 1];
                    uint32_t l0 = bL[jf * 2], l1 = bL[jf * 2 + 1];
                    MMA16816(A.a[i][jf], aH[i], h0, h1);
                    MMA16816(A.a[i][jf], aH[i], l0, l1);
                    MMA16816(A.a[i][jf], aL[i], h0, h1);
                }
            }
        }
        __syncthreads();
        if (kt + 2 < NT) issue(kt + 2, kt & 1);
    }
}

// QKV projections merged into one launch: blockIdx.z in {0,1,2}
__global__ __launch_bounds__(256, 2) void gemm_qkv(
    const float* __restrict__ bq, const float* __restrict__ bk,
    const float* __restrict__ bv)
{
    extern __shared__ char sm[];
    const uint32_t sbase = smem_u32(sm);
    const int lane = threadIdx.x & 31;
    const int wid  = threadIdx.x >> 5;
    const int m0 = blockIdx.y << 7;
    const int n0 = blockIdx.x << 6;
    const int z  = blockIdx.z;

    size_t aHi, aLo, bHi, bLo, dH, dL;
    const float* bias;
    if (z == 0) { aHi = OFF_XQ_HI; aLo = OFF_XQ_LO; bHi = OFF_WQ_HI; bLo = OFF_WQ_LO;
                  dH = OFF_AQ_HI; dL = OFF_AQ_LO; bias = bq; }
    else if (z == 1) { aHi = OFF_XK_HI; aLo = OFF_XK_LO; bHi = OFF_WK_HI; bLo = OFF_WK_LO;
                  dH = OFF_AK_HI; dL = OFF_AK_LO; bias = bk; }
    else { aHi = OFF_XV_HI; aLo = OFF_XV_LO; bHi = OFF_WV_HI; bLo = OFF_WV_LO;
                  dH = OFF_AV_HI; dL = OFF_AV_LO; bias = bv; }

    GemmAcc A;
    gemm_core(sbase, aHi, aLo, bHi, bLo, m0, n0, A);

    const int mrb = m0 + (wid & 1) * 64;
    const int ncb = n0 + (wid >> 1) * 16;
    __nv_bfloat16* hp = g_bf + dH;
    __nv_bfloat16* lp = g_bf + dL;
#pragma unroll
    for (int i = 0; i < 4; i++) {
        int r0 = mrb + i * 16 + (lane >> 2);
#pragma unroll
        for (int jf = 0; jf < 2; jf++) {
            int c = ncb + jf * 8 + (lane & 3) * 2;
            float bx = __ldg(bias + c);
            float by = __ldg(bias + c + 1);
            int h = c >> 6, d = c & 63;
            size_t ix0 = ((size_t)(((r0 >> 11) << 4) | h) << 17)
                       + ((size_t)(r0 & 2047) << 6) + d;
            split_store2(hp, lp, ix0, A.a[i][jf][0] + bx, A.a[i][jf][1] + by);
            split_store2(hp, lp, ix0 + (8ull << 6), A.a[i][jf][2] + bx, A.a[i][jf][3] + by);
        }
    }
}

// Output projection: ctx (split bf16) x Wo^T + bo -> fp32 out
__global__ __launch_bounds__(256, 2) void gemm_out(
    const float* __restrict__ bias, float* __restrict__ ext)
{
    extern __shared__ char sm[];
    const uint32_t sbase = smem_u32(sm);
    const int lane = threadIdx.x & 31;
    const int wid  = threadIdx.x >> 5;
    const int m0 = blockIdx.y << 7;
    const int n0 = blockIdx.x << 6;

    GemmAcc A;
    gemm_core(sbase, OFF_CTX_HI, OFF_CTX_LO, OFF_WO_HI, OFF_WO_LO, m0, n0, A);

    const int mrb = m0 + (wid & 1) * 64;
    const int ncb = n0 + (wid >> 1) * 16;
#pragma unroll
    for (int i = 0; i < 4; i++) {
        int r0 = mrb + i * 16 + (lane >> 2);
#pragma unroll
        for (int jf = 0; jf < 2; jf++) {
            int cb = ncb + jf * 8 + (lane & 3) * 2;
            float bx = __ldg(bias + cb);
            float by = __ldg(bias + cb + 1);
            float2 o0 = make_float2(A.a[i][jf][0] + bx, A.a[i][jf][1] + by);
            float2 o1 = make_float2(A.a[i][jf][2] + bx, A.a[i][jf][3] + by);
            *reinterpret_cast<float2*>(ext + (size_t)r0 * 1024 + cb)       = o0;
            *reinterpret_cast<float2*>(ext + (size_t)(r0 + 8) * 1024 + cb) = o1;
        }
    }
}

// ---------------------------------------------------------------------------
// Tensor-core flash attention (split-bf16, fixed-scale softmax).
// CTA: 128 queries x one (b,h). 8 warps x 16-q tiles. Key tiles of 64.
// 3-stage cp.async pipeline (wait ladder 2/1/0); unchanged (near floor).
// ---------------------------------------------------------------------------
#define ATT_STAGE 32768            // KH 8K | KL 8K | VH 8K | VL 8K
#define ATT_NSTG  3
#define ATT_SMEM  (ATT_NSTG * ATT_STAGE)  // 96 KB

__global__ __launch_bounds__(256, 2) void attn_tc()
{
    extern __shared__ char sm[];
    const uint32_t sb = smem_u32(sm);
    const int tid = threadIdx.x, lane = tid & 31, wid = tid >> 5;
    const int bh = blockIdx.y;
    const int q0 = blockIdx.x << 7;

    const __nv_bfloat16* Qh = g_bf + OFF_AQ_HI + ((size_t)bh << 17) + ((size_t)q0 << 6);
    const __nv_bfloat16* Ql = g_bf + OFF_AQ_LO + ((size_t)bh << 17) + ((size_t)q0 << 6);
    const __nv_bfloat16* Kh = g_bf + OFF_AK_HI + ((size_t)bh << 17);
    const __nv_bfloat16* Kl = g_bf + OFF_AK_LO + ((size_t)bh << 17);
    const __nv_bfloat16* Vh = g_bf + OFF_AV_HI + ((size_t)bh << 17);
    const __nv_bfloat16* Vl = g_bf + OFF_AV_LO + ((size_t)bh << 17);

    // ---- stage Q tile (128x64 hi+lo) into stage-0 smem, then to registers ----
#pragma unroll
    for (int j = 0; j < 8; j++) {
        int c = tid + j * 256;
        int t = c >> 10;
        int r = (c >> 3) & 127;
        int cb = c & 7;
        uint32_t dst = sb + t * 16384 + r * 128 + ((cb ^ (r & 7)) << 4);
        const __nv_bfloat16* src = (t ? Ql : Qh) + (size_t)r * 64 + cb * 8;
        CP_ASYNC16(dst, src);
    }
    CP_COMMIT(); CP_WAIT(0);
    __syncthreads();

    uint32_t aQh[4][4], aQl[4][4];
    {
        int row = (wid << 4) + (lane & 7) + ((lane >> 3) & 1) * 8;
#pragma unroll
        for (int ks = 0; ks < 4; ks++) {
            int cb = ks * 2 + (lane >> 4);
            uint32_t ad = sb + row * 128 + ((cb ^ (row & 7)) << 4);
            LDSM4(aQh[ks], ad);
            LDSM4(aQl[ks], ad + 16384);
        }
    }
    __syncthreads();

    // ---- KV pipeline ----
    auto issue = [&](int kt, int stg) {
        const int k0 = kt << 6;
#pragma unroll
        for (int j = 0; j < 8; j++) {
            int c = tid + j * 256;
            int t = c >> 9;
            int r = (c >> 3) & 63;
            int cb = c & 7;
            uint32_t dst = sb + stg * ATT_STAGE + t * 8192 + r * 128 + ((cb ^ (r & 7)) << 4);
            const __nv_bfloat16* base = (t == 0) ? Kh : (t == 1) ? Kl : (t == 2) ? Vh : Vl;
            CP_ASYNC16(dst, base + (size_t)(k0 + r) * 64 + cb * 8);
        }
        CP_COMMIT();
    };
    issue(0, 0);
    issue(1, 1);
    issue(2, 2);

    float O[8][4];
#pragma unroll
    for (int f = 0; f < 8; f++)
#pragma unroll
        for (int e = 0; e < 4; e++) O[f][e] = 0.f;
    float l0 = 0.f, l1 = 0.f;
    const float cs = 0.125f * 1.4426950408889634f;

    const int krow = (lane & 7) + (lane >> 4) * 8;
    const int kcb  = (lane >> 3) & 1;
    const int vrow = (lane & 7) + ((lane >> 3) & 1) * 8;
    const int vcb  = lane >> 4;

    int stg = 0;  // kt % 3
    for (int kt = 0; kt < 32; kt++) {
        if (kt < 30) CP_WAIT(2);
        else if (kt == 30) CP_WAIT(1);
        else CP_WAIT(0);
        __syncthreads();
        const uint32_t st = sb + stg * ATT_STAGE;

        // two key-halves of 32 keys each: compute S-half, softmax, PV-half
#pragma unroll
        for (int h2 = 0; h2 < 2; h2++) {
            float S[4][4];
#pragma unroll
            for (int f = 0; f < 4; f++)
#pragma unroll
                for (int e = 0; e < 4; e++) S[f][e] = 0.f;

#pragma unroll
            for (int ks = 0; ks < 4; ks++) {
#pragma unroll
                for (int gg = 0; gg < 2; gg++) {
                    int g = 2 * h2 + gg;
                    int rr = g * 16 + krow;
                    int cb = ks * 2 + kcb;
                    uint32_t ad = st + rr * 128 + ((cb ^ (rr & 7)) << 4);
                    uint32_t KH[4], KL[4];
                    LDSM4(KH, ad);
                    LDSM4(KL, ad + 8192);
                    MMA16816(S[2 * gg],     aQh[ks], KH[0], KH[1]);
                    MMA16816(S[2 * gg],     aQh[ks], KL[0], KL[1]);
                    MMA16816(S[2 * gg],     aQl[ks], KH[0], KH[1]);
                    MMA16816(S[2 * gg + 1], aQh[ks], KH[2], KH[3]);
                    MMA16816(S[2 * gg + 1], aQh[ks], KL[2], KL[3]);
                    MMA16816(S[2 * gg + 1], aQl[ks], KH[2], KH[3]);
                }
            }

#pragma unroll
            for (int f = 0; f < 4; f++) {
#pragma unroll
                for (int e = 0; e < 4; e++) S[f][e] = ex2(S[f][e] * cs);
                l0 += S[f][0] + S[f][1];
                l1 += S[f][2] + S[f][3];
            }

#pragma unroll
            for (int jj = 0; jj < 2; jj++) {
                int kk = 2 * h2 + jj;
                uint32_t pH[4], pL[4];
                float* Sa = S[2 * jj];
                float* Sb = S[2 * jj + 1];
                pH[0] = packbf(Sa[0], Sa[1]);
                pH[1] = packbf(Sa[2], Sa[3]);
                pH[2] = packbf(Sb[0], Sb[1]);
                pH[3] = packbf(Sb[2], Sb[3]);
                pL[0] = packbf(Sa[0] - bflo(pH[0]), Sa[1] - bfhi(pH[0]));
                pL[1] = packbf(Sa[2] - bflo(pH[1]), Sa[3] - bfhi(pH[1]));
                pL[2] = packbf(Sb[0] - bflo(pH[2]), Sb[1] - bfhi(pH[2]));
                pL[3] = packbf(Sb[2] - bflo(pH[3]), Sb[3] - bfhi(pH[3]));
#pragma unroll
                for (int dp = 0; dp < 4; dp++) {
                    int rr = kk * 16 + vrow;
                    int cb = dp * 2 + vcb;
                    uint32_t ad = st + 16384 + rr * 128 + ((cb ^ (rr & 7)) << 4);
                    uint32_t VH[4], VL[4];
                    LDSM4T(VH, ad);
                    LDSM4T(VL, ad + 8192);
                    MMA16816(O[2 * dp],     pH, VH[0], VH[1]);
                    MMA16816(O[2 * dp],     pH, VL[0], VL[1]);
                    MMA16816(O[2 * dp],     pL, VH[0], VH[1]);
                    MMA16816(O[2 * dp + 1], pH, VH[2], VH[3]);
                    MMA16816(O[2 * dp + 1], pH, VL[2], VL[3]);
                    MMA16816(O[2 * dp + 1], pL, VH[2], VH[3]);
                }
            }
        }

        __syncthreads();
        if (kt + 3 < 32) issue(kt + 3, stg);   // tile kt+3 reuses stage kt%3
        stg = (stg == 2) ? 0 : stg + 1;
    }

    // ---- epilogue: normalize and write ctx as bf16 hi/lo [b,s,1024] ----
    l0 += __shfl_xor_sync(0xffffffffu, l0, 1);
    l0 += __shfl_xor_sync(0xffffffffu, l0, 2);
    l1 += __shfl_xor_sync(0xffffffffu, l1, 1);
    l1 += __shfl_xor_sync(0xffffffffu, l1, 2);
    const float inv0 = 1.f / l0;
    const float inv1 = 1.f / l1;

    const int b = bh >> 4, h = bh & 15;
    const int r0g = b * 2048 + q0 + (wid << 4) + (lane >> 2);
    __nv_bfloat16* ch = g_bf + OFF_CTX_HI;
    __nv_bfloat16* cl = g_bf + OFF_CTX_LO;
#pragma unroll
    for (int f = 0; f < 8; f++) {
        int col = (h << 6) + f * 8 + (lane & 3) * 2;
        split_store2(ch, cl, (size_t)r0g * 1024 + col,
                     O[f][0] * inv0, O[f][1] * inv0);
        split_store2(ch, cl, (size_t)(r0g + 8) * 1024 + col,
                     O[f][2] * inv1, O[f][3] * inv1);
    }
}

// ---------------------------------------------------------------------------
extern "C" void kernel_launch(void* const* d_in, const int* in_sizes, int n_in,
                              void* d_out, int out_size)
{
    const float* query = (const float*)d_in[0];
    const float* key   = (const float*)d_in[1];
    const float* value = (const float*)d_in[2];
    const float* Wq = (const float*)d_in[3];
    const float* bq = (const float*)d_in[4];
    const float* Wk = (const float*)d_in[5];
    const float* bk = (const float*)d_in[6];
    const float* Wv = (const float*)d_in[7];
    const float* bv = (const float*)d_in[8];
    const float* Wo = (const float*)d_in[9];
    const float* bo = (const float*)d_in[10];
    float* out = (float*)d_out;

    cudaFuncSetAttribute(gemm_qkv, cudaFuncAttributeMaxDynamicSharedMemorySize, GEMM_SMEM);
    cudaFuncSetAttribute(gemm_out, cudaFuncAttributeMaxDynamicSharedMemorySize, GEMM_SMEM);
    cudaFuncSetAttribute(attn_tc,  cudaFuncAttributeMaxDynamicSharedMemorySize, ATT_SMEM);

    convert_all<<<16384, 256>>>(query, key, value, Wq, Wk, Wv, Wo);

    gemm_qkv<<<dim3(DM / 64, MROWS / 128, 3), 256, GEMM_SMEM>>>(bq, bk, bv);

    attn_tc<<<dim3(SEQ / 128, BATCH * NH), 256, ATT_SMEM>>>();

    gemm_out<<<dim3(DM / 64, MROWS / 128), 256, GEMM_SMEM>>>(bo, out);
}

// round 12
// speedup vs baseline: 1.1227x; 1.0873x over previous
#include <cuda_runtime.h>
#include <cuda_bf16.h>
#include <cstdint>
#include <cstddef>

// Problem constants: B=2, S=2048, D_MODEL=1024, H=16, d_k=64
#define BATCH 2
#define SEQ 2048
#define DM 1024
#define NH 16
#define MROWS (BATCH * SEQ)   // 4096

// ---------------------------------------------------------------------------
// bf16 pool (element offsets)
// ---------------------------------------------------------------------------
#define SZ_ACT (4096ull * 1024ull)
#define SZ_W   (1024ull * 1024ull)
#define OFF_XQ_HI 0ull
#define OFF_XQ_LO (OFF_XQ_HI + SZ_ACT)
#define OFF_XK_HI (OFF_XQ_LO + SZ_ACT)
#define OFF_XK_LO (OFF_XK_HI + SZ_ACT)
#define OFF_XV_HI (OFF_XK_LO + SZ_ACT)
#define OFF_XV_LO (OFF_XV_HI + SZ_ACT)
#define OFF_WQ_HI (OFF_XV_LO + SZ_ACT)
#define OFF_WQ_LO (OFF_WQ_HI + SZ_W)
#define OFF_WK_HI (OFF_WQ_LO + SZ_W)
#define OFF_WK_LO (OFF_WK_HI + SZ_W)
#define OFF_WV_HI (OFF_WK_LO + SZ_W)
#define OFF_WV_LO (OFF_WV_HI + SZ_W)
#define OFF_WO_HI (OFF_WV_LO + SZ_W)
#define OFF_WO_LO (OFF_WO_HI + SZ_W)
#define OFF_CTX_HI (OFF_WO_LO + SZ_W)
#define OFF_CTX_LO (OFF_CTX_HI + SZ_ACT)
// head-major attention operands: [b*16+h][s][64]
#define OFF_AQ_HI (OFF_CTX_LO + SZ_ACT)
#define OFF_AQ_LO (OFF_AQ_HI + SZ_ACT)
#define OFF_AK_HI (OFF_AQ_LO + SZ_ACT)
#define OFF_AK_LO (OFF_AK_HI + SZ_ACT)
#define OFF_AV_HI (OFF_AK_LO + SZ_ACT)
#define OFF_AV_LO (OFF_AV_HI + SZ_ACT)
#define BF_TOTAL  (OFF_AV_LO + SZ_ACT)
__device__ __nv_bfloat16 g_bf[BF_TOTAL];

// ---------------------------------------------------------------------------
// PTX helpers — baseline ISA only (cp.async / ldmatrix / mma.sync / cvt)
// ---------------------------------------------------------------------------
__device__ __forceinline__ uint32_t smem_u32(const void* p) {
    uint32_t a;
    asm("{ .reg .u64 t; cvta.to.shared.u64 t, %1; cvt.u32.u64 %0, t; }"
        : "=r"(a) : "l"(p));
    return a;
}

#define CP_ASYNC16(dst, src) \
    asm volatile("cp.async.cg.shared.global [%0], [%1], 16;" :: "r"(dst), "l"(src))
#define CP_COMMIT() asm volatile("cp.async.commit_group;" ::: "memory")
#define CP_WAIT(N)  asm volatile("cp.async.wait_group %0;" :: "n"(N) : "memory")

#define LDSM4(R, addr) \
    asm volatile("ldmatrix.sync.aligned.m8n8.x4.shared.b16 {%0,%1,%2,%3}, [%4];" \
        : "=r"((R)[0]), "=r"((R)[1]), "=r"((R)[2]), "=r"((R)[3]) : "r"(addr))
#define LDSM4T(R, addr) \
    asm volatile("ldmatrix.sync.aligned.m8n8.x4.trans.shared.b16 {%0,%1,%2,%3}, [%4];" \
        : "=r"((R)[0]), "=r"((R)[1]), "=r"((R)[2]), "=r"((R)[3]) : "r"(addr))

#define MMA16816(C, A, b0, b1) \
    asm volatile("mma.sync.aligned.m16n8k16.row.col.f32.bf16.bf16.f32 " \
        "{%0,%1,%2,%3}, {%4,%5,%6,%7}, {%8,%9}, {%0,%1,%2,%3};" \
        : "+f"((C)[0]), "+f"((C)[1]), "+f"((C)[2]), "+f"((C)[3]) \
        : "r"((A)[0]), "r"((A)[1]), "r"((A)[2]), "r"((A)[3]), "r"(b0), "r"(b1))

__device__ __forceinline__ float ex2(float x) {
    float r; asm("ex2.approx.ftz.f32 %0, %1;" : "=f"(r) : "f"(x)); return r;
}
__device__ __forceinline__ uint32_t packbf(float lo, float hi) {
    uint32_t u;
    asm("cvt.rn.bf16x2.f32 %0, %1, %2;" : "=r"(u) : "f"(hi), "f"(lo));
    return u;
}
__device__ __forceinline__ float bflo(uint32_t u) { return __uint_as_float(u << 16); }
__device__ __forceinline__ float bfhi(uint32_t u) { return __uint_as_float(u & 0xffff0000u); }

__device__ __forceinline__ void split_store2(
    __nv_bfloat16* hp, __nv_bfloat16* lp, size_t idx, float a, float b)
{
    __nv_bfloat16 ha = __float2bfloat16(a);
    __nv_bfloat16 hb = __float2bfloat16(b);
    __nv_bfloat16 la = __float2bfloat16(a - __bfloat162float(ha));
    __nv_bfloat16 lb = __float2bfloat16(b - __bfloat162float(hb));
    *reinterpret_cast<__nv_bfloat162*>(hp + idx) = __nv_bfloat162(ha, hb);
    *reinterpret_cast<__nv_bfloat162*>(lp + idx) = __nv_bfloat162(la, lb);
}

// ---------------------------------------------------------------------------
// ONE merged fp32 -> bf16 hi/lo split conversion for all 7 tensors.
// ---------------------------------------------------------------------------
__global__ __launch_bounds__(256) void convert_all(
    const float* __restrict__ q, const float* __restrict__ k,
    const float* __restrict__ v, const float* __restrict__ wq,
    const float* __restrict__ wk, const float* __restrict__ wv,
    const float* __restrict__ wo)
{
    const int blk = blockIdx.x;
    const float* src;
    size_t hiOff, loOff, base;
    if (blk < 12288) {
        int t = blk >> 12;
        src = (t == 0) ? q : (t == 1) ? k : v;
        hiOff = (t == 0) ? OFF_XQ_HI : (t == 1) ? OFF_XK_HI : OFF_XV_HI;
        loOff = (t == 0) ? OFF_XQ_LO : (t == 1) ? OFF_XK_LO : OFF_XV_LO;
        base = ((size_t)(blk & 4095)) << 10;
    } else {
        int t = (blk - 12288) >> 10;
        src = (t == 0) ? wq : (t == 1) ? wk : (t == 2) ? wv : wo;
        hiOff = (t == 0) ? OFF_WQ_HI : (t == 1) ? OFF_WK_HI
              : (t == 2) ? OFF_WV_HI : OFF_WO_HI;
        loOff = (t == 0) ? OFF_WQ_LO : (t == 1) ? OFF_WK_LO
              : (t == 2) ? OFF_WV_LO : OFF_WO_LO;
        base = ((size_t)((blk - 12288) & 1023)) << 10;
    }
    size_t i = base + (size_t)threadIdx.x * 4;
    float4 x = *(const float4*)(src + i);
    __nv_bfloat16 h[4], l[4];
    float vv[4] = {x.x, x.y, x.z, x.w};
#pragma unroll
    for (int j = 0; j < 4; j++) {
        h[j] = __float2bfloat16(vv[j]);
        l[j] = __float2bfloat16(vv[j] - __bfloat162float(h[j]));
    }
    *reinterpret_cast<__nv_bfloat162*>(g_bf + hiOff + i)     = __nv_bfloat162(h[0], h[1]);
    *reinterpret_cast<__nv_bfloat162*>(g_bf + hiOff + i + 2) = __nv_bfloat162(h[2], h[3]);
    *reinterpret_cast<__nv_bfloat162*>(g_bf + loOff + i)     = __nv_bfloat162(l[0], l[1]);
    *reinterpret_cast<__nv_bfloat162*>(g_bf + loOff + i + 2) = __nv_bfloat162(l[2], l[3]);
}

// ---------------------------------------------------------------------------
// GEMM core: R8 shape — CTA tile 128x128, 256 threads, 2(M)x4(N) warps,
// warp tile 64x32, 2-stage pipeline, double barrier. Register-lean inner
// loop: A fragments loaded in two halves so only 2 (of 4) A row-frags are
// live at once -> ~112 arch regs -> 2 CTAs/SM under __launch_bounds__(256,2).
// ---------------------------------------------------------------------------
#define NT 32
#define KT 32
#define ROWB 80
#define TILEB (128 * ROWB)
#define STAGEB (4 * TILEB)
#define GEMM_SMEM (2 * STAGEB)   // 81920

struct GemmAcc { float a[4][4][4]; };

__device__ __forceinline__ void gemm_core(
    uint32_t sbase, size_t aHi, size_t aLo, size_t bHi, size_t bLo,
    int m0, int n0, GemmAcc& A)
{
    const int tid  = threadIdx.x;
    const int lane = tid & 31;
    const int wid  = tid >> 5;

    const __nv_bfloat16* gp0 = g_bf + aHi + (size_t)m0 * 1024;
    const __nv_bfloat16* gp1 = g_bf + aLo + (size_t)m0 * 1024;
    const __nv_bfloat16* gp2 = g_bf + bHi + (size_t)n0 * 1024;
    const __nv_bfloat16* gp3 = g_bf + bLo + (size_t)n0 * 1024;

    auto issue = [&](int kt, int stage) {
        const int kc = kt * KT;
#pragma unroll
        for (int j = 0; j < 8; j++) {
            int c    = tid + j * 256;
            int tile = c >> 9;
            int r    = (c >> 2) & 127;
            int qq   = c & 3;
            uint32_t dst = sbase + stage * STAGEB + tile * TILEB + r * ROWB + qq * 16;
            const __nv_bfloat16* base =
                (tile == 0) ? gp0 : (tile == 1) ? gp1 : (tile == 2) ? gp2 : gp3;
            CP_ASYNC16(dst, base + (size_t)r * 1024 + kc + qq * 8);
        }
        CP_COMMIT();
    };

    issue(0, 0);
    issue(1, 1);

    const int wm = wid & 1;
    const int wn = wid >> 1;
    const int a_row  = (lane & 7) + ((lane >> 3) & 1) * 8;
    const int a_colb = ((lane >> 4) * 8) * 2;
    const int b_row  = (lane & 7) + ((lane >> 4)) * 8;
    const int b_colb = (((lane >> 3) & 1) * 8) * 2;

#pragma unroll
    for (int i = 0; i < 4; i++)
#pragma unroll
        for (int j = 0; j < 4; j++)
#pragma unroll
            for (int e = 0; e < 4; e++) A.a[i][j][e] = 0.f;

    for (int kt = 0; kt < NT; kt++) {
        if (kt == NT - 1) CP_WAIT(0); else CP_WAIT(1);
        __syncthreads();
        const uint32_t st = sbase + (kt & 1) * STAGEB;

#pragma unroll
        for (int ks = 0; ks < 2; ks++) {
            uint32_t bH[2][4], bL[2][4];
#pragma unroll
            for (int j = 0; j < 2; j++) {
                uint32_t bd = st + 2 * TILEB +
                              (wn * 32 + j * 16 + b_row) * ROWB + ks * 32 + b_colb;
                LDSM4(bH[j], bd);
                LDSM4(bL[j], bd + TILEB);
            }
            // A in two halves: only 2 row-fragments (hi+lo) live at a time
#pragma unroll
            for (int ih = 0; ih < 2; ih++) {
                uint32_t aH[2][4], aL[2][4];
#pragma unroll
                for (int i = 0; i < 2; i++) {
                    uint32_t ad = st + (wm * 64 + (ih * 2 + i) * 16 + a_row) * ROWB
                                + ks * 32 + a_colb;
                    LDSM4(aH[i], ad);
                    LDSM4(aL[i], ad + TILEB);
                }
#pragma unroll
                for (int i = 0; i < 2; i++) {
#pragma unroll
                    for (int jf = 0; jf < 4; jf++) {
                        uint32_t h0 = bH[jf >> 1][(jf & 1) * 2];
                        uint32_t h1 = bH[jf >> 1][(jf & 1) * 2 + 1];
                        uint32_t l0 = bL[jf >> 1][(jf & 1) * 2];
                        uint32_t l1 = bL[jf >> 1][(jf & 1) * 2 + 1];
                        float* acc = A.a[ih * 2 + i][jf];
                        MMA16816(acc, aH[i], h0, h1);
                        MMA16816(acc, aH[i], l0, l1);
                        MMA16816(acc, aL[i], h0, h1);
                    }
                }
            }
        }
        __syncthreads();
        if (kt + 2 < NT) issue(kt + 2, kt & 1);
    }
}

// QKV projections merged into one launch: blockIdx.z in {0,1,2}
__global__ __launch_bounds__(256, 2) void gemm_qkv(
    const float* __restrict__ bq, const float* __restrict__ bk,
    const float* __restrict__ bv)
{
    extern __shared__ char sm[];
    const uint32_t sbase = smem_u32(sm);
    const int lane = threadIdx.x & 31;
    const int wid  = threadIdx.x >> 5;
    const int m0 = blockIdx.y << 7;
    const int n0 = blockIdx.x << 7;
    const int z  = blockIdx.z;

    size_t aHi, aLo, bHi, bLo, dH, dL;
    const float* bias;
    if (z == 0) { aHi = OFF_XQ_HI; aLo = OFF_XQ_LO; bHi = OFF_WQ_HI; bLo = OFF_WQ_LO;
                  dH = OFF_AQ_HI; dL = OFF_AQ_LO; bias = bq; }
    else if (z == 1) { aHi = OFF_XK_HI; aLo = OFF_XK_LO; bHi = OFF_WK_HI; bLo = OFF_WK_LO;
                  dH = OFF_AK_HI; dL = OFF_AK_LO; bias = bk; }
    else { aHi = OFF_XV_HI; aLo = OFF_XV_LO; bHi = OFF_WV_HI; bLo = OFF_WV_LO;
                  dH = OFF_AV_HI; dL = OFF_AV_LO; bias = bv; }

    GemmAcc A;
    gemm_core(sbase, aHi, aLo, bHi, bLo, m0, n0, A);

    const int mrb = m0 + (wid & 1) * 64;
    const int ncb = n0 + (wid >> 1) * 32;
    __nv_bfloat16* hp = g_bf + dH;
    __nv_bfloat16* lp = g_bf + dL;
#pragma unroll
    for (int i = 0; i < 4; i++) {
        int r0 = mrb + i * 16 + (lane >> 2);
#pragma unroll
        for (int jf = 0; jf < 4; jf++) {
            int c = ncb + jf * 8 + (lane & 3) * 2;
            float bx = __ldg(bias + c);
            float by = __ldg(bias + c + 1);
            int h = c >> 6, d = c & 63;
            size_t ix0 = ((size_t)(((r0 >> 11) << 4) | h) << 17)
                       + ((size_t)(r0 & 2047) << 6) + d;
            split_store2(hp, lp, ix0, A.a[i][jf][0] + bx, A.a[i][jf][1] + by);
            split_store2(hp, lp, ix0 + (8ull << 6), A.a[i][jf][2] + bx, A.a[i][jf][3] + by);
        }
    }
}

// Output projection: ctx (split bf16) x Wo^T + bo -> fp32 out
__global__ __launch_bounds__(256, 2) void gemm_out(
    const float* __restrict__ bias, float* __restrict__ ext)
{
    extern __shared__ char sm[];
    const uint32_t sbase = smem_u32(sm);
    const int lane = threadIdx.x & 31;
    const int wid  = threadIdx.x >> 5;
    const int m0 = blockIdx.y << 7;
    const int n0 = blockIdx.x << 7;

    GemmAcc A;
    gemm_core(sbase, OFF_CTX_HI, OFF_CTX_LO, OFF_WO_HI, OFF_WO_LO, m0, n0, A);

    const int mrb = m0 + (wid & 1) * 64;
    const int ncb = n0 + (wid >> 1) * 32;
#pragma unroll
    for (int i = 0; i < 4; i++) {
        int r0 = mrb + i * 16 + (lane >> 2);
#pragma unroll
        for (int jf = 0; jf < 4; jf++) {
            int cb = ncb + jf * 8 + (lane & 3) * 2;
            float bx = __ldg(bias + cb);
            float by = __ldg(bias + cb + 1);
            float2 o0 = make_float2(A.a[i][jf][0] + bx, A.a[i][jf][1] + by);
            float2 o1 = make_float2(A.a[i][jf][2] + bx, A.a[i][jf][3] + by);
            *reinterpret_cast<float2*>(ext + (size_t)r0 * 1024 + cb)       = o0;
            *reinterpret_cast<float2*>(ext + (size_t)(r0 + 8) * 1024 + cb) = o1;
        }
    }
}

// ---------------------------------------------------------------------------
// Tensor-core flash attention (split-bf16, fixed-scale softmax).
// CTA: 128 queries x one (b,h). 8 warps x 16-q tiles. Key tiles of 64.
// 3-stage cp.async pipeline (wait ladder 2/1/0); unchanged (near floor).
// ---------------------------------------------------------------------------
#define ATT_STAGE 32768            // KH 8K | KL 8K | VH 8K | VL 8K
#define ATT_NSTG  3
#define ATT_SMEM  (ATT_NSTG * ATT_STAGE)  // 96 KB

__global__ __launch_bounds__(256, 2) void attn_tc()
{
    extern __shared__ char sm[];
    const uint32_t sb = smem_u32(sm);
    const int tid = threadIdx.x, lane = tid & 31, wid = tid >> 5;
    const int bh = blockIdx.y;
    const int q0 = blockIdx.x << 7;

    const __nv_bfloat16* Qh = g_bf + OFF_AQ_HI + ((size_t)bh << 17) + ((size_t)q0 << 6);
    const __nv_bfloat16* Ql = g_bf + OFF_AQ_LO + ((size_t)bh << 17) + ((size_t)q0 << 6);
    const __nv_bfloat16* Kh = g_bf + OFF_AK_HI + ((size_t)bh << 17);
    const __nv_bfloat16* Kl = g_bf + OFF_AK_LO + ((size_t)bh << 17);
    const __nv_bfloat16* Vh = g_bf + OFF_AV_HI + ((size_t)bh << 17);
    const __nv_bfloat16* Vl = g_bf + OFF_AV_LO + ((size_t)bh << 17);

    // ---- stage Q tile (128x64 hi+lo) into stage-0 smem, then to registers ----
#pragma unroll
    for (int j = 0; j < 8; j++) {
        int c = tid + j * 256;
        int t = c >> 10;
        int r = (c >> 3) & 127;
        int cb = c & 7;
        uint32_t dst = sb + t * 16384 + r * 128 + ((cb ^ (r & 7)) << 4);
        const __nv_bfloat16* src = (t ? Ql : Qh) + (size_t)r * 64 + cb * 8;
        CP_ASYNC16(dst, src);
    }
    CP_COMMIT(); CP_WAIT(0);
    __syncthreads();

    uint32_t aQh[4][4], aQl[4][4];
    {
        int row = (wid << 4) + (lane & 7) + ((lane >> 3) & 1) * 8;
#pragma unroll
        for (int ks = 0; ks < 4; ks++) {
            int cb = ks * 2 + (lane >> 4);
            uint32_t ad = sb + row * 128 + ((cb ^ (row & 7)) << 4);
            LDSM4(aQh[ks], ad);
            LDSM4(aQl[ks], ad + 16384);
        }
    }
    __syncthreads();

    // ---- KV pipeline ----
    auto issue = [&](int kt, int stg) {
        const int k0 = kt << 6;
#pragma unroll
        for (int j = 0; j < 8; j++) {
            int c = tid + j * 256;
            int t = c >> 9;
            int r = (c >> 3) & 63;
            int cb = c & 7;
            uint32_t dst = sb + stg * ATT_STAGE + t * 8192 + r * 128 + ((cb ^ (r & 7)) << 4);
            const __nv_bfloat16* base = (t == 0) ? Kh : (t == 1) ? Kl : (t == 2) ? Vh : Vl;
            CP_ASYNC16(dst, base + (size_t)(k0 + r) * 64 + cb * 8);
        }
        CP_COMMIT();
    };
    issue(0, 0);
    issue(1, 1);
    issue(2, 2);

    float O[8][4];
#pragma unroll
    for (int f = 0; f < 8; f++)
#pragma unroll
        for (int e = 0; e < 4; e++) O[f][e] = 0.f;
    float l0 = 0.f, l1 = 0.f;
    const float cs = 0.125f * 1.4426950408889634f;

    const int krow = (lane & 7) + (lane >> 4) * 8;
    const int kcb  = (lane >> 3) & 1;
    const int vrow = (lane & 7) + ((lane >> 3) & 1) * 8;
    const int vcb  = lane >> 4;

    int stg = 0;  // kt % 3
    for (int kt = 0; kt < 32; kt++) {
        if (kt < 30) CP_WAIT(2);
        else if (kt == 30) CP_WAIT(1);
        else CP_WAIT(0);
        __syncthreads();
        const uint32_t st = sb + stg * ATT_STAGE;

        // two key-halves of 32 keys each: compute S-half, softmax, PV-half
#pragma unroll
        for (int h2 = 0; h2 < 2; h2++) {
            float S[4][4];
#pragma unroll
            for (int f = 0; f < 4; f++)
#pragma unroll
                for (int e = 0; e < 4; e++) S[f][e] = 0.f;

#pragma unroll
            for (int ks = 0; ks < 4; ks++) {
#pragma unroll
                for (int gg = 0; gg < 2; gg++) {
                    int g = 2 * h2 + gg;
                    int rr = g * 16 + krow;
                    int cb = ks * 2 + kcb;
                    uint32_t ad = st + rr * 128 + ((cb ^ (rr & 7)) << 4);
                    uint32_t KH[4], KL[4];
                    LDSM4(KH, ad);
                    LDSM4(KL, ad + 8192);
                    MMA16816(S[2 * gg],     aQh[ks], KH[0], KH[1]);
                    MMA16816(S[2 * gg],     aQh[ks], KL[0], KL[1]);
                    MMA16816(S[2 * gg],     aQl[ks], KH[0], KH[1]);
                    MMA16816(S[2 * gg + 1], aQh[ks], KH[2], KH[3]);
                    MMA16816(S[2 * gg + 1], aQh[ks], KL[2], KL[3]);
                    MMA16816(S[2 * gg + 1], aQl[ks], KH[2], KH[3]);
                }
            }

#pragma unroll
            for (int f = 0; f < 4; f++) {
#pragma unroll
                for (int e = 0; e < 4; e++) S[f][e] = ex2(S[f][e] * cs);
                l0 += S[f][0] + S[f][1];
                l1 += S[f][2] + S[f][3];
            }

#pragma unroll
            for (int jj = 0; jj < 2; jj++) {
                int kk = 2 * h2 + jj;
                uint32_t pH[4], pL[4];
                float* Sa = S[2 * jj];
                float* Sb = S[2 * jj + 1];
                pH[0] = packbf(Sa[0], Sa[1]);
                pH[1] = packbf(Sa[2], Sa[3]);
                pH[2] = packbf(Sb[0], Sb[1]);
                pH[3] = packbf(Sb[2], Sb[3]);
                pL[0] = packbf(Sa[0] - bflo(pH[0]), Sa[1] - bfhi(pH[0]));
                pL[1] = packbf(Sa[2] - bflo(pH[1]), Sa[3] - bfhi(pH[1]));
                pL[2] = packbf(Sb[0] - bflo(pH[2]), Sb[1] - bfhi(pH[2]));
                pL[3] = packbf(Sb[2] - bflo(pH[3]), Sb[3] - bfhi(pH[3]));
#pragma unroll
                for (int dp = 0; dp < 4; dp++) {
                    int rr = kk * 16 + vrow;
                    int cb = dp * 2 + vcb;
                    uint32_t ad = st + 16384 + rr * 128 + ((cb ^ (rr & 7)) << 4);
                    uint32_t VH[4], VL[4];
                    LDSM4T(VH, ad);
                    LDSM4T(VL, ad + 8192);
                    MMA16816(O[2 * dp],     pH, VH[0], VH[1]);
                    MMA16816(O[2 * dp],     pH, VL[0], VL[1]);
                    MMA16816(O[2 * dp],     pL, VH[0], VH[1]);
                    MMA16816(O[2 * dp + 1], pH, VH[2], VH[3]);
                    MMA16816(O[2 * dp + 1], pH, VL[2], VL[3]);
                    MMA16816(O[2 * dp + 1], pL, VH[2], VH[3]);
                }
            }
        }

        __syncthreads();
        if (kt + 3 < 32) issue(kt + 3, stg);   // tile kt+3 reuses stage kt%3
        stg = (stg == 2) ? 0 : stg + 1;
    }

    // ---- epilogue: normalize and write ctx as bf16 hi/lo [b,s,1024] ----
    l0 += __shfl_xor_sync(0xffffffffu, l0, 1);
    l0 += __shfl_xor_sync(0xffffffffu, l0, 2);
    l1 += __shfl_xor_sync(0xffffffffu, l1, 1);
    l1 += __shfl_xor_sync(0xffffffffu, l1, 2);
    const float inv0 = 1.f / l0;
    const float inv1 = 1.f / l1;

    const int b = bh >> 4, h = bh & 15;
    const int r0g = b * 2048 + q0 + (wid << 4) + (lane >> 2);
    __nv_bfloat16* ch = g_bf + OFF_CTX_HI;
    __nv_bfloat16* cl = g_bf + OFF_CTX_LO;
#pragma unroll
    for (int f = 0; f < 8; f++) {
        int col = (h << 6) + f * 8 + (lane & 3) * 2;
        split_store2(ch, cl, (size_t)r0g * 1024 + col,
                     O[f][0] * inv0, O[f][1] * inv0);
        split_store2(ch, cl, (size_t)(r0g + 8) * 1024 + col,
                     O[f][2] * inv1, O[f][3] * inv1);
    }
}

// ---------------------------------------------------------------------------
extern "C" void kernel_launch(void* const* d_in, const int* in_sizes, int n_in,
                              void* d_out, int out_size)
{
    const float* query = (const float*)d_in[0];
    const float* key   = (const float*)d_in[1];
    const float* value = (const float*)d_in[2];
    const float* Wq = (const float*)d_in[3];
    const float* bq = (const float*)d_in[4];
    const float* Wk = (const float*)d_in[5];
    const float* bk = (const float*)d_in[6];
    const float* Wv = (const float*)d_in[7];
    const float* bv = (const float*)d_in[8];
    const float* Wo = (const float*)d_in[9];
    const float* bo = (const float*)d_in[10];
    float* out = (float*)d_out;

    cudaFuncSetAttribute(gemm_qkv, cudaFuncAttributeMaxDynamicSharedMemorySize, GEMM_SMEM);
    cudaFuncSetAttribute(gemm_out, cudaFuncAttributeMaxDynamicSharedMemorySize, GEMM_SMEM);
    cudaFuncSetAttribute(attn_tc,  cudaFuncAttributeMaxDynamicSharedMemorySize, ATT_SMEM);

    convert_all<<<16384, 256>>>(query, key, value, Wq, Wk, Wv, Wo);

    gemm_qkv<<<dim3(DM / 128, MROWS / 128, 3), 256, GEMM_SMEM>>>(bq, bk, bv);

    attn_tc<<<dim3(SEQ / 128, BATCH * NH), 256, ATT_SMEM>>>();

    gemm_out<<<dim3(DM / 128, MROWS / 128), 256, GEMM_SMEM>>>(bo, out);
}

// round 13
// speedup vs baseline: 1.1635x; 1.0364x over previous
#include <cuda_runtime.h>
#include <cuda_bf16.h>
#include <cstdint>
#include <cstddef>

// Problem constants: B=2, S=2048, D_MODEL=1024, H=16, d_k=64
#define BATCH 2
#define SEQ 2048
#define DM 1024
#define NH 16
#define MROWS (BATCH * SEQ)   // 4096

// ---------------------------------------------------------------------------
// bf16 pool (element offsets)
// ---------------------------------------------------------------------------
#define SZ_ACT (4096ull * 1024ull)
#define SZ_W   (1024ull * 1024ull)
#define OFF_XQ_HI 0ull
#define OFF_XQ_LO (OFF_XQ_HI + SZ_ACT)
#define OFF_XK_HI (OFF_XQ_LO + SZ_ACT)
#define OFF_XK_LO (OFF_XK_HI + SZ_ACT)
#define OFF_XV_HI (OFF_XK_LO + SZ_ACT)
#define OFF_XV_LO (OFF_XV_HI + SZ_ACT)
#define OFF_WQ_HI (OFF_XV_LO + SZ_ACT)
#define OFF_WQ_LO (OFF_WQ_HI + SZ_W)
#define OFF_WK_HI (OFF_WQ_LO + SZ_W)
#define OFF_WK_LO (OFF_WK_HI + SZ_W)
#define OFF_WV_HI (OFF_WK_LO + SZ_W)
#define OFF_WV_LO (OFF_WV_HI + SZ_W)
#define OFF_WO_HI (OFF_WV_LO + SZ_W)
#define OFF_WO_LO (OFF_WO_HI + SZ_W)
#define OFF_CTX_HI (OFF_WO_LO + SZ_W)
#define OFF_CTX_LO (OFF_CTX_HI + SZ_ACT)
// head-major attention operands: [b*16+h][s][64]
#define OFF_AQ_HI (OFF_CTX_LO + SZ_ACT)
#define OFF_AQ_LO (OFF_AQ_HI + SZ_ACT)
#define OFF_AK_HI (OFF_AQ_LO + SZ_ACT)
#define OFF_AK_LO (OFF_AK_HI + SZ_ACT)
#define OFF_AV_HI (OFF_AK_LO + SZ_ACT)
#define OFF_AV_LO (OFF_AV_HI + SZ_ACT)
#define BF_TOTAL  (OFF_AV_LO + SZ_ACT)
__device__ __nv_bfloat16 g_bf[BF_TOTAL];

// ---------------------------------------------------------------------------
// PTX helpers — baseline ISA only (cp.async / ldmatrix / mma.sync / cvt)
// ---------------------------------------------------------------------------
__device__ __forceinline__ uint32_t smem_u32(const void* p) {
    uint32_t a;
    asm("{ .reg .u64 t; cvta.to.shared.u64 t, %1; cvt.u32.u64 %0, t; }"
        : "=r"(a) : "l"(p));
    return a;
}

#define CP_ASYNC16(dst, src) \
    asm volatile("cp.async.cg.shared.global [%0], [%1], 16;" :: "r"(dst), "l"(src))
#define CP_COMMIT() asm volatile("cp.async.commit_group;" ::: "memory")
#define CP_WAIT(N)  asm volatile("cp.async.wait_group %0;" :: "n"(N) : "memory")

#define LDSM4(R, addr) \
    asm volatile("ldmatrix.sync.aligned.m8n8.x4.shared.b16 {%0,%1,%2,%3}, [%4];" \
        : "=r"((R)[0]), "=r"((R)[1]), "=r"((R)[2]), "=r"((R)[3]) : "r"(addr))
#define LDSM4T(R, addr) \
    asm volatile("ldmatrix.sync.aligned.m8n8.x4.trans.shared.b16 {%0,%1,%2,%3}, [%4];" \
        : "=r"((R)[0]), "=r"((R)[1]), "=r"((R)[2]), "=r"((R)[3]) : "r"(addr))

#define MMA16816(C, A, b0, b1) \
    asm volatile("mma.sync.aligned.m16n8k16.row.col.f32.bf16.bf16.f32 " \
        "{%0,%1,%2,%3}, {%4,%5,%6,%7}, {%8,%9}, {%0,%1,%2,%3};" \
        : "+f"((C)[0]), "+f"((C)[1]), "+f"((C)[2]), "+f"((C)[3]) \
        : "r"((A)[0]), "r"((A)[1]), "r"((A)[2]), "r"((A)[3]), "r"(b0), "r"(b1))

__device__ __forceinline__ float ex2(float x) {
    float r; asm("ex2.approx.ftz.f32 %0, %1;" : "=f"(r) : "f"(x)); return r;
}
__device__ __forceinline__ uint32_t packbf(float lo, float hi) {
    uint32_t u;
    asm("cvt.rn.bf16x2.f32 %0, %1, %2;" : "=r"(u) : "f"(hi), "f"(lo));
    return u;
}
__device__ __forceinline__ float bflo(uint32_t u) { return __uint_as_float(u << 16); }
__device__ __forceinline__ float bfhi(uint32_t u) { return __uint_as_float(u & 0xffff0000u); }

__device__ __forceinline__ void split_store2(
    __nv_bfloat16* hp, __nv_bfloat16* lp, size_t idx, float a, float b)
{
    __nv_bfloat16 ha = __float2bfloat16(a);
    __nv_bfloat16 hb = __float2bfloat16(b);
    __nv_bfloat16 la = __float2bfloat16(a - __bfloat162float(ha));
    __nv_bfloat16 lb = __float2bfloat16(b - __bfloat162float(hb));
    *reinterpret_cast<__nv_bfloat162*>(hp + idx) = __nv_bfloat162(ha, hb);
    *reinterpret_cast<__nv_bfloat162*>(lp + idx) = __nv_bfloat162(la, lb);
}

// ---------------------------------------------------------------------------
// ONE merged fp32 -> bf16 hi/lo split conversion for all 7 tensors.
// ---------------------------------------------------------------------------
__global__ __launch_bounds__(256) void convert_all(
    const float* __restrict__ q, const float* __restrict__ k,
    const float* __restrict__ v, const float* __restrict__ wq,
    const float* __restrict__ wk, const float* __restrict__ wv,
    const float* __restrict__ wo)
{
    const int blk = blockIdx.x;
    const float* src;
    size_t hiOff, loOff, base;
    if (blk < 12288) {
        int t = blk >> 12;
        src = (t == 0) ? q : (t == 1) ? k : v;
        hiOff = (t == 0) ? OFF_XQ_HI : (t == 1) ? OFF_XK_HI : OFF_XV_HI;
        loOff = (t == 0) ? OFF_XQ_LO : (t == 1) ? OFF_XK_LO : OFF_XV_LO;
        base = ((size_t)(blk & 4095)) << 10;
    } else {
        int t = (blk - 12288) >> 10;
        src = (t == 0) ? wq : (t == 1) ? wk : (t == 2) ? wv : wo;
        hiOff = (t == 0) ? OFF_WQ_HI : (t == 1) ? OFF_WK_HI
              : (t == 2) ? OFF_WV_HI : OFF_WO_HI;
        loOff = (t == 0) ? OFF_WQ_LO : (t == 1) ? OFF_WK_LO
              : (t == 2) ? OFF_WV_LO : OFF_WO_LO;
        base = ((size_t)((blk - 12288) & 1023)) << 10;
    }
    size_t i = base + (size_t)threadIdx.x * 4;
    float4 x = *(const float4*)(src + i);
    __nv_bfloat16 h[4], l[4];
    float vv[4] = {x.x, x.y, x.z, x.w};
#pragma unroll
    for (int j = 0; j < 4; j++) {
        h[j] = __float2bfloat16(vv[j]);
        l[j] = __float2bfloat16(vv[j] - __bfloat162float(h[j]));
    }
    *reinterpret_cast<__nv_bfloat162*>(g_bf + hiOff + i)     = __nv_bfloat162(h[0], h[1]);
    *reinterpret_cast<__nv_bfloat162*>(g_bf + hiOff + i + 2) = __nv_bfloat162(h[2], h[3]);
    *reinterpret_cast<__nv_bfloat162*>(g_bf + loOff + i)     = __nv_bfloat162(l[0], l[1]);
    *reinterpret_cast<__nv_bfloat162*>(g_bf + loOff + i + 2) = __nv_bfloat162(l[2], l[3]);
}

// ---------------------------------------------------------------------------
// GEMM core: CTA tile 128x128, 256 threads, 2(M)x4(N) warps, warp tile 64x32.
// XOR-swizzled unpadded smem: tile = 128 rows x 32 bf16 packed as 64 lines of
// 128B (2 rows/line), chunk ^= line&7  ->  8 KB/tile, conflict-free LDSM.
// 3-stage pipeline (wait ladder 2/1/0, stage rotation) at 2 CTAs/SM.
// ---------------------------------------------------------------------------
#define NT 32
#define KT 32
#define TILEB 8192
#define STAGEB (4 * TILEB)        // 32768
#define GNSTG 3
#define GEMM_SMEM (GNSTG * STAGEB)  // 98304

// logical (row 0..127, chunk 0..3 of 16B) -> swizzled byte offset in tile
__device__ __forceinline__ uint32_t gsw(int r, int c) {
    uint32_t line = (uint32_t)(r >> 1);
    uint32_t cil  = ((uint32_t)(r & 1) << 2) | (uint32_t)c;
    return (line << 7) + ((cil ^ (line & 7)) << 4);
}

struct GemmAcc { float a[4][4][4]; };

__device__ __forceinline__ void gemm_core(
    uint32_t sbase, size_t aHi, size_t aLo, size_t bHi, size_t bLo,
    int m0, int n0, GemmAcc& A)
{
    const int tid  = threadIdx.x;
    const int lane = tid & 31;
    const int wid  = tid >> 5;

    const __nv_bfloat16* gp0 = g_bf + aHi + (size_t)m0 * 1024;
    const __nv_bfloat16* gp1 = g_bf + aLo + (size_t)m0 * 1024;
    const __nv_bfloat16* gp2 = g_bf + bHi + (size_t)n0 * 1024;
    const __nv_bfloat16* gp3 = g_bf + bLo + (size_t)n0 * 1024;

    auto issue = [&](int kt, int stage) {
        const int kc = kt * KT;
#pragma unroll
        for (int j = 0; j < 8; j++) {
            int c    = tid + j * 256;
            int tile = c >> 9;
            int w    = c & 511;
            int r    = w >> 2;
            int qq   = w & 3;
            uint32_t dst = sbase + stage * STAGEB + tile * TILEB + gsw(r, qq);
            const __nv_bfloat16* base =
                (tile == 0) ? gp0 : (tile == 1) ? gp1 : (tile == 2) ? gp2 : gp3;
            CP_ASYNC16(dst, base + (size_t)r * 1024 + kc + qq * 8);
        }
        CP_COMMIT();
    };

    issue(0, 0);
    issue(1, 1);
    issue(2, 2);

    const int wm = wid & 1;
    const int wn = wid >> 1;
    const int a_row = (lane & 7) + ((lane >> 3) & 1) * 8;
    const int a_chk = (lane >> 4);           // + ks*2
    const int b_row = (lane & 7) + ((lane >> 4)) * 8;
    const int b_chk = ((lane >> 3) & 1);     // + ks*2

#pragma unroll
    for (int i = 0; i < 4; i++)
#pragma unroll
        for (int j = 0; j < 4; j++)
#pragma unroll
            for (int e = 0; e < 4; e++) A.a[i][j][e] = 0.f;

    int stg = 0;   // kt % 3
    for (int kt = 0; kt < NT; kt++) {
        if (kt < NT - 2) CP_WAIT(2);
        else if (kt == NT - 2) CP_WAIT(1);
        else CP_WAIT(0);
        __syncthreads();
        const uint32_t st = sbase + stg * STAGEB;

#pragma unroll
        for (int ks = 0; ks < 2; ks++) {
            uint32_t bH[2][4], bL[2][4];
#pragma unroll
            for (int j = 0; j < 2; j++) {
                uint32_t bd = st + 2 * TILEB +
                              gsw(wn * 32 + j * 16 + b_row, ks * 2 + b_chk);
                LDSM4(bH[j], bd);
                LDSM4(bL[j], bd + TILEB);
            }
            // A in two halves: only 2 row-fragments (hi+lo) live at a time
#pragma unroll
            for (int ih = 0; ih < 2; ih++) {
                uint32_t aH[2][4], aL[2][4];
#pragma unroll
                for (int i = 0; i < 2; i++) {
                    uint32_t ad = st +
                        gsw(wm * 64 + (ih * 2 + i) * 16 + a_row, ks * 2 + a_chk);
                    LDSM4(aH[i], ad);
                    LDSM4(aL[i], ad + TILEB);
                }
#pragma unroll
                for (int i = 0; i < 2; i++) {
#pragma unroll
                    for (int jf = 0; jf < 4; jf++) {
                        uint32_t h0 = bH[jf >> 1][(jf & 1) * 2];
                        uint32_t h1 = bH[jf >> 1][(jf & 1) * 2 + 1];
                        uint32_t l0 = bL[jf >> 1][(jf & 1) * 2];
                        uint32_t l1 = bL[jf >> 1][(jf & 1) * 2 + 1];
                        float* acc = A.a[ih * 2 + i][jf];
                        MMA16816(acc, aH[i], h0, h1);
                        MMA16816(acc, aH[i], l0, l1);
                        MMA16816(acc, aL[i], h0, h1);
                    }
                }
            }
        }
        __syncthreads();
        if (kt + 3 < NT) issue(kt + 3, stg);   // reuse stage just consumed
        stg = (stg == 2) ? 0 : stg + 1;
    }
}

// QKV projections merged into one launch: blockIdx.z in {0,1,2}
__global__ __launch_bounds__(256, 2) void gemm_qkv(
    const float* __restrict__ bq, const float* __restrict__ bk,
    const float* __restrict__ bv)
{
    extern __shared__ char sm[];
    const uint32_t sbase = smem_u32(sm);
    const int lane = threadIdx.x & 31;
    const int wid  = threadIdx.x >> 5;
    const int m0 = blockIdx.y << 7;
    const int n0 = blockIdx.x << 7;
    const int z  = blockIdx.z;

    size_t aHi, aLo, bHi, bLo, dH, dL;
    const float* bias;
    if (z == 0) { aHi = OFF_XQ_HI; aLo = OFF_XQ_LO; bHi = OFF_WQ_HI; bLo = OFF_WQ_LO;
                  dH = OFF_AQ_HI; dL = OFF_AQ_LO; bias = bq; }
    else if (z == 1) { aHi = OFF_XK_HI; aLo = OFF_XK_LO; bHi = OFF_WK_HI; bLo = OFF_WK_LO;
                  dH = OFF_AK_HI; dL = OFF_AK_LO; bias = bk; }
    else { aHi = OFF_XV_HI; aLo = OFF_XV_LO; bHi = OFF_WV_HI; bLo = OFF_WV_LO;
                  dH = OFF_AV_HI; dL = OFF_AV_LO; bias = bv; }

    GemmAcc A;
    gemm_core(sbase, aHi, aLo, bHi, bLo, m0, n0, A);

    const int mrb = m0 + (wid & 1) * 64;
    const int ncb = n0 + (wid >> 1) * 32;
    __nv_bfloat16* hp = g_bf + dH;
    __nv_bfloat16* lp = g_bf + dL;
#pragma unroll
    for (int i = 0; i < 4; i++) {
        int r0 = mrb + i * 16 + (lane >> 2);
#pragma unroll
        for (int jf = 0; jf < 4; jf++) {
            int c = ncb + jf * 8 + (lane & 3) * 2;
            float bx = __ldg(bias + c);
            float by = __ldg(bias + c + 1);
            int h = c >> 6, d = c & 63;
            size_t ix0 = ((size_t)(((r0 >> 11) << 4) | h) << 17)
                       + ((size_t)(r0 & 2047) << 6) + d;
            split_store2(hp, lp, ix0, A.a[i][jf][0] + bx, A.a[i][jf][1] + by);
            split_store2(hp, lp, ix0 + (8ull << 6), A.a[i][jf][2] + bx, A.a[i][jf][3] + by);
        }
    }
}

// Output projection: ctx (split bf16) x Wo^T + bo -> fp32 out
__global__ __launch_bounds__(256, 2) void gemm_out(
    const float* __restrict__ bias, float* __restrict__ ext)
{
    extern __shared__ char sm[];
    const uint32_t sbase = smem_u32(sm);
    const int lane = threadIdx.x & 31;
    const int wid  = threadIdx.x >> 5;
    const int m0 = blockIdx.y << 7;
    const int n0 = blockIdx.x << 7;

    GemmAcc A;
    gemm_core(sbase, OFF_CTX_HI, OFF_CTX_LO, OFF_WO_HI, OFF_WO_LO, m0, n0, A);

    const int mrb = m0 + (wid & 1) * 64;
    const int ncb = n0 + (wid >> 1) * 32;
#pragma unroll
    for (int i = 0; i < 4; i++) {
        int r0 = mrb + i * 16 + (lane >> 2);
#pragma unroll
        for (int jf = 0; jf < 4; jf++) {
            int cb = ncb + jf * 8 + (lane & 3) * 2;
            float bx = __ldg(bias + cb);
            float by = __ldg(bias + cb + 1);
            float2 o0 = make_float2(A.a[i][jf][0] + bx, A.a[i][jf][1] + by);
            float2 o1 = make_float2(A.a[i][jf][2] + bx, A.a[i][jf][3] + by);
            *reinterpret_cast<float2*>(ext + (size_t)r0 * 1024 + cb)       = o0;
            *reinterpret_cast<float2*>(ext + (size_t)(r0 + 8) * 1024 + cb) = o1;
        }
    }
}

// ---------------------------------------------------------------------------
// Tensor-core flash attention (split-bf16, fixed-scale softmax).
// CTA: 128 queries x one (b,h). 8 warps x 16-q tiles. Key tiles of 64.
// 3-stage cp.async pipeline (wait ladder 2/1/0); unchanged (near floor).
// ---------------------------------------------------------------------------
#define ATT_STAGE 32768            // KH 8K | KL 8K | VH 8K | VL 8K
#define ATT_NSTG  3
#define ATT_SMEM  (ATT_NSTG * ATT_STAGE)  // 96 KB

__global__ __launch_bounds__(256, 2) void attn_tc()
{
    extern __shared__ char sm[];
    const uint32_t sb = smem_u32(sm);
    const int tid = threadIdx.x, lane = tid & 31, wid = tid >> 5;
    const int bh = blockIdx.y;
    const int q0 = blockIdx.x << 7;

    const __nv_bfloat16* Qh = g_bf + OFF_AQ_HI + ((size_t)bh << 17) + ((size_t)q0 << 6);
    const __nv_bfloat16* Ql = g_bf + OFF_AQ_LO + ((size_t)bh << 17) + ((size_t)q0 << 6);
    const __nv_bfloat16* Kh = g_bf + OFF_AK_HI + ((size_t)bh << 17);
    const __nv_bfloat16* Kl = g_bf + OFF_AK_LO + ((size_t)bh << 17);
    const __nv_bfloat16* Vh = g_bf + OFF_AV_HI + ((size_t)bh << 17);
    const __nv_bfloat16* Vl = g_bf + OFF_AV_LO + ((size_t)bh << 17);

    // ---- stage Q tile (128x64 hi+lo) into stage-0 smem, then to registers ----
#pragma unroll
    for (int j = 0; j < 8; j++) {
        int c = tid + j * 256;
        int t = c >> 10;
        int r = (c >> 3) & 127;
        int cb = c & 7;
        uint32_t dst = sb + t * 16384 + r * 128 + ((cb ^ (r & 7)) << 4);
        const __nv_bfloat16* src = (t ? Ql : Qh) + (size_t)r * 64 + cb * 8;
        CP_ASYNC16(dst, src);
    }
    CP_COMMIT(); CP_WAIT(0);
    __syncthreads();

    uint32_t aQh[4][4], aQl[4][4];
    {
        int row = (wid << 4) + (lane & 7) + ((lane >> 3) & 1) * 8;
#pragma unroll
        for (int ks = 0; ks < 4; ks++) {
            int cb = ks * 2 + (lane >> 4);
            uint32_t ad = sb + row * 128 + ((cb ^ (row & 7)) << 4);
            LDSM4(aQh[ks], ad);
            LDSM4(aQl[ks], ad + 16384);
        }
    }
    __syncthreads();

    // ---- KV pipeline ----
    auto issue = [&](int kt, int stg) {
        const int k0 = kt << 6;
#pragma unroll
        for (int j = 0; j < 8; j++) {
            int c = tid + j * 256;
            int t = c >> 9;
            int r = (c >> 3) & 63;
            int cb = c & 7;
            uint32_t dst = sb + stg * ATT_STAGE + t * 8192 + r * 128 + ((cb ^ (r & 7)) << 4);
            const __nv_bfloat16* base = (t == 0) ? Kh : (t == 1) ? Kl : (t == 2) ? Vh : Vl;
            CP_ASYNC16(dst, base + (size_t)(k0 + r) * 64 + cb * 8);
        }
        CP_COMMIT();
    };
    issue(0, 0);
    issue(1, 1);
    issue(2, 2);

    float O[8][4];
#pragma unroll
    for (int f = 0; f < 8; f++)
#pragma unroll
        for (int e = 0; e < 4; e++) O[f][e] = 0.f;
    float l0 = 0.f, l1 = 0.f;
    const float cs = 0.125f * 1.4426950408889634f;

    const int krow = (lane & 7) + (lane >> 4) * 8;
    const int kcb  = (lane >> 3) & 1;
    const int vrow = (lane & 7) + ((lane >> 3) & 1) * 8;
    const int vcb  = lane >> 4;

    int stg = 0;  // kt % 3
    for (int kt = 0; kt < 32; kt++) {
        if (kt < 30) CP_WAIT(2);
        else if (kt == 30) CP_WAIT(1);
        else CP_WAIT(0);
        __syncthreads();
        const uint32_t st = sb + stg * ATT_STAGE;

        // two key-halves of 32 keys each: compute S-half, softmax, PV-half
#pragma unroll
        for (int h2 = 0; h2 < 2; h2++) {
            float S[4][4];
#pragma unroll
            for (int f = 0; f < 4; f++)
#pragma unroll
                for (int e = 0; e < 4; e++) S[f][e] = 0.f;

#pragma unroll
            for (int ks = 0; ks < 4; ks++) {
#pragma unroll
                for (int gg = 0; gg < 2; gg++) {
                    int g = 2 * h2 + gg;
                    int rr = g * 16 + krow;
                    int cb = ks * 2 + kcb;
                    uint32_t ad = st + rr * 128 + ((cb ^ (rr & 7)) << 4);
                    uint32_t KH[4], KL[4];
                    LDSM4(KH, ad);
                    LDSM4(KL, ad + 8192);
                    MMA16816(S[2 * gg],     aQh[ks], KH[0], KH[1]);
                    MMA16816(S[2 * gg],     aQh[ks], KL[0], KL[1]);
                    MMA16816(S[2 * gg],     aQl[ks], KH[0], KH[1]);
                    MMA16816(S[2 * gg + 1], aQh[ks], KH[2], KH[3]);
                    MMA16816(S[2 * gg + 1], aQh[ks], KL[2], KL[3]);
                    MMA16816(S[2 * gg + 1], aQl[ks], KH[2], KH[3]);
                }
            }

#pragma unroll
            for (int f = 0; f < 4; f++) {
#pragma unroll
                for (int e = 0; e < 4; e++) S[f][e] = ex2(S[f][e] * cs);
                l0 += S[f][0] + S[f][1];
                l1 += S[f][2] + S[f][3];
            }

#pragma unroll
            for (int jj = 0; jj < 2; jj++) {
                int kk = 2 * h2 + jj;
                uint32_t pH[4], pL[4];
                float* Sa = S[2 * jj];
                float* Sb = S[2 * jj + 1];
                pH[0] = packbf(Sa[0], Sa[1]);
                pH[1] = packbf(Sa[2], Sa[3]);
                pH[2] = packbf(Sb[0], Sb[1]);
                pH[3] = packbf(Sb[2], Sb[3]);
                pL[0] = packbf(Sa[0] - bflo(pH[0]), Sa[1] - bfhi(pH[0]));
                pL[1] = packbf(Sa[2] - bflo(pH[1]), Sa[3] - bfhi(pH[1]));
                pL[2] = packbf(Sb[0] - bflo(pH[2]), Sb[1] - bfhi(pH[2]));
                pL[3] = packbf(Sb[2] - bflo(pH[3]), Sb[3] - bfhi(pH[3]));
#pragma unroll
                for (int dp = 0; dp < 4; dp++) {
                    int rr = kk * 16 + vrow;
                    int cb = dp * 2 + vcb;
                    uint32_t ad = st + 16384 + rr * 128 + ((cb ^ (rr & 7)) << 4);
                    uint32_t VH[4], VL[4];
                    LDSM4T(VH, ad);
                    LDSM4T(VL, ad + 8192);
                    MMA16816(O[2 * dp],     pH, VH[0], VH[1]);
                    MMA16816(O[2 * dp],     pH, VL[0], VL[1]);
                    MMA16816(O[2 * dp],     pL, VH[0], VH[1]);
                    MMA16816(O[2 * dp + 1], pH, VH[2], VH[3]);
                    MMA16816(O[2 * dp + 1], pH, VL[2], VL[3]);
                    MMA16816(O[2 * dp + 1], pL, VH[2], VH[3]);
                }
            }
        }

        __syncthreads();
        if (kt + 3 < 32) issue(kt + 3, stg);   // tile kt+3 reuses stage kt%3
        stg = (stg == 2) ? 0 : stg + 1;
    }

    // ---- epilogue: normalize and write ctx as bf16 hi/lo [b,s,1024] ----
    l0 += __shfl_xor_sync(0xffffffffu, l0, 1);
    l0 += __shfl_xor_sync(0xffffffffu, l0, 2);
    l1 += __shfl_xor_sync(0xffffffffu, l1, 1);
    l1 += __shfl_xor_sync(0xffffffffu, l1, 2);
    const float inv0 = 1.f / l0;
    const float inv1 = 1.f / l1;

    const int b = bh >> 4, h = bh & 15;
    const int r0g = b * 2048 + q0 + (wid << 4) + (lane >> 2);
    __nv_bfloat16* ch = g_bf + OFF_CTX_HI;
    __nv_bfloat16* cl = g_bf + OFF_CTX_LO;
#pragma unroll
    for (int f = 0; f < 8; f++) {
        int col = (h << 6) + f * 8 + (lane & 3) * 2;
        split_store2(ch, cl, (size_t)r0g * 1024 + col,
                     O[f][0] * inv0, O[f][1] * inv0);
        split_store2(ch, cl, (size_t)(r0g + 8) * 1024 + col,
                     O[f][2] * inv1, O[f][3] * inv1);
    }
}

// ---------------------------------------------------------------------------
extern "C" void kernel_launch(void* const* d_in, const int* in_sizes, int n_in,
                              void* d_out, int out_size)
{
    const float* query = (const float*)d_in[0];
    const float* key   = (const float*)d_in[1];
    const float* value = (const float*)d_in[2];
    const float* Wq = (const float*)d_in[3];
    const float* bq = (const float*)d_in[4];
    const float* Wk = (const float*)d_in[5];
    const float* bk = (const float*)d_in[6];
    const float* Wv = (const float*)d_in[7];
    const float* bv = (const float*)d_in[8];
    const float* Wo = (const float*)d_in[9];
    const float* bo = (const float*)d_in[10];
    float* out = (float*)d_out;

    cudaFuncSetAttribute(gemm_qkv, cudaFuncAttributeMaxDynamicSharedMemorySize, GEMM_SMEM);
    cudaFuncSetAttribute(gemm_out, cudaFuncAttributeMaxDynamicSharedMemorySize, GEMM_SMEM);
    cudaFuncSetAttribute(attn_tc,  cudaFuncAttributeMaxDynamicSharedMemorySize, ATT_SMEM);

    convert_all<<<16384, 256>>>(query, key, value, Wq, Wk, Wv, Wo);

    gemm_qkv<<<dim3(DM / 128, MROWS / 128, 3), 256, GEMM_SMEM>>>(bq, bk, bv);

    attn_tc<<<dim3(SEQ / 128, BATCH * NH), 256, ATT_SMEM>>>();

    gemm_out<<<dim3(DM / 128, MROWS / 128), 256, GEMM_SMEM>>>(bo, out);
}

// round 15
// speedup vs baseline: 1.1671x; 1.0031x over previous
#include <cuda_runtime.h>
#include <cuda_bf16.h>
#include <cstdint>
#include <cstddef>

// Problem constants: B=2, S=2048, D_MODEL=1024, H=16, d_k=64
#define BATCH 2
#define SEQ 2048
#define DM 1024
#define NH 16
#define MROWS (BATCH * SEQ)   // 4096

// ---------------------------------------------------------------------------
// bf16 pool (element offsets)
// ---------------------------------------------------------------------------
#define SZ_ACT (4096ull * 1024ull)
#define SZ_W   (1024ull * 1024ull)
#define OFF_XQ_HI 0ull
#define OFF_XQ_LO (OFF_XQ_HI + SZ_ACT)
#define OFF_XK_HI (OFF_XQ_LO + SZ_ACT)
#define OFF_XK_LO (OFF_XK_HI + SZ_ACT)
#define OFF_XV_HI (OFF_XK_LO + SZ_ACT)
#define OFF_XV_LO (OFF_XV_HI + SZ_ACT)
#define OFF_WQ_HI (OFF_XV_LO + SZ_ACT)
#define OFF_WQ_LO (OFF_WQ_HI + SZ_W)
#define OFF_WK_HI (OFF_WQ_LO + SZ_W)
#define OFF_WK_LO (OFF_WK_HI + SZ_W)
#define OFF_WV_HI (OFF_WK_LO + SZ_W)
#define OFF_WV_LO (OFF_WV_HI + SZ_W)
#define OFF_WO_HI (OFF_WV_LO + SZ_W)
#define OFF_WO_LO (OFF_WO_HI + SZ_W)
#define OFF_CTX_HI (OFF_WO_LO + SZ_W)
#define OFF_CTX_LO (OFF_CTX_HI + SZ_ACT)
// head-major attention operands: [b*16+h][s][64]
#define OFF_AQ_HI (OFF_CTX_LO + SZ_ACT)
#define OFF_AQ_LO (OFF_AQ_HI + SZ_ACT)
#define OFF_AK_HI (OFF_AQ_LO + SZ_ACT)
#define OFF_AK_LO (OFF_AK_HI + SZ_ACT)
#define OFF_AV_HI (OFF_AK_LO + SZ_ACT)
#define OFF_AV_LO (OFF_AV_HI + SZ_ACT)
#define BF_TOTAL  (OFF_AV_LO + SZ_ACT)
__device__ __nv_bfloat16 g_bf[BF_TOTAL];

// ---------------------------------------------------------------------------
// PTX helpers — baseline ISA only (cp.async / ldmatrix / mma.sync / cvt)
// ---------------------------------------------------------------------------
__device__ __forceinline__ uint32_t smem_u32(const void* p) {
    uint32_t a;
    asm("{ .reg .u64 t; cvta.to.shared.u64 t, %1; cvt.u32.u64 %0, t; }"
        : "=r"(a) : "l"(p));
    return a;
}

#define CP_ASYNC16(dst, src) \
    asm volatile("cp.async.cg.shared.global [%0], [%1], 16;" :: "r"(dst), "l"(src))
#define CP_COMMIT() asm volatile("cp.async.commit_group;" ::: "memory")
#define CP_WAIT(N)  asm volatile("cp.async.wait_group %0;" :: "n"(N) : "memory")

#define LDSM4(R, addr) \
    asm volatile("ldmatrix.sync.aligned.m8n8.x4.shared.b16 {%0,%1,%2,%3}, [%4];" \
        : "=r"((R)[0]), "=r"((R)[1]), "=r"((R)[2]), "=r"((R)[3]) : "r"(addr))
#define LDSM4T(R, addr) \
    asm volatile("ldmatrix.sync.aligned.m8n8.x4.trans.shared.b16 {%0,%1,%2,%3}, [%4];" \
        : "=r"((R)[0]), "=r"((R)[1]), "=r"((R)[2]), "=r"((R)[3]) : "r"(addr))

#define MMA16816(C, A, b0, b1) \
    asm volatile("mma.sync.aligned.m16n8k16.row.col.f32.bf16.bf16.f32 " \
        "{%0,%1,%2,%3}, {%4,%5,%6,%7}, {%8,%9}, {%0,%1,%2,%3};" \
        : "+f"((C)[0]), "+f"((C)[1]), "+f"((C)[2]), "+f"((C)[3]) \
        : "r"((A)[0]), "r"((A)[1]), "r"((A)[2]), "r"((A)[3]), "r"(b0), "r"(b1))

__device__ __forceinline__ float ex2(float x) {
    float r; asm("ex2.approx.ftz.f32 %0, %1;" : "=f"(r) : "f"(x)); return r;
}
__device__ __forceinline__ uint32_t packbf(float lo, float hi) {
    uint32_t u;
    asm("cvt.rn.bf16x2.f32 %0, %1, %2;" : "=r"(u) : "f"(hi), "f"(lo));
    return u;
}
__device__ __forceinline__ float bflo(uint32_t u) { return __uint_as_float(u << 16); }
__device__ __forceinline__ float bfhi(uint32_t u) { return __uint_as_float(u & 0xffff0000u); }

__device__ __forceinline__ void split_store2(
    __nv_bfloat16* hp, __nv_bfloat16* lp, size_t idx, float a, float b)
{
    __nv_bfloat16 ha = __float2bfloat16(a);
    __nv_bfloat16 hb = __float2bfloat16(b);
    __nv_bfloat16 la = __float2bfloat16(a - __bfloat162float(ha));
    __nv_bfloat16 lb = __float2bfloat16(b - __bfloat162float(hb));
    *reinterpret_cast<__nv_bfloat162*>(hp + idx) = __nv_bfloat162(ha, hb);
    *reinterpret_cast<__nv_bfloat162*>(lp + idx) = __nv_bfloat162(la, lb);
}

// ---------------------------------------------------------------------------
// ONE merged fp32 -> bf16 hi/lo split conversion for all 7 tensors.
// ---------------------------------------------------------------------------
__global__ __launch_bounds__(256) void convert_all(
    const float* __restrict__ q, const float* __restrict__ k,
    const float* __restrict__ v, const float* __restrict__ wq,
    const float* __restrict__ wk, const float* __restrict__ wv,
    const float* __restrict__ wo)
{
    const int blk = blockIdx.x;
    const float* src;
    size_t hiOff, loOff, base;
    if (blk < 12288) {
        int t = blk >> 12;
        src = (t == 0) ? q : (t == 1) ? k : v;
        hiOff = (t == 0) ? OFF_XQ_HI : (t == 1) ? OFF_XK_HI : OFF_XV_HI;
        loOff = (t == 0) ? OFF_XQ_LO : (t == 1) ? OFF_XK_LO : OFF_XV_LO;
        base = ((size_t)(blk & 4095)) << 10;
    } else {
        int t = (blk - 12288) >> 10;
        src = (t == 0) ? wq : (t == 1) ? wk : (t == 2) ? wv : wo;
        hiOff = (t == 0) ? OFF_WQ_HI : (t == 1) ? OFF_WK_HI
              : (t == 2) ? OFF_WV_HI : OFF_WO_HI;
        loOff = (t == 0) ? OFF_WQ_LO : (t == 1) ? OFF_WK_LO
              : (t == 2) ? OFF_WV_LO : OFF_WO_LO;
        base = ((size_t)((blk - 12288) & 1023)) << 10;
    }
    size_t i = base + (size_t)threadIdx.x * 4;
    float4 x = *(const float4*)(src + i);
    __nv_bfloat16 h[4], l[4];
    float vv[4] = {x.x, x.y, x.z, x.w};
#pragma unroll
    for (int j = 0; j < 4; j++) {
        h[j] = __float2bfloat16(vv[j]);
        l[j] = __float2bfloat16(vv[j] - __bfloat162float(h[j]));
    }
    *reinterpret_cast<__nv_bfloat162*>(g_bf + hiOff + i)     = __nv_bfloat162(h[0], h[1]);
    *reinterpret_cast<__nv_bfloat162*>(g_bf + hiOff + i + 2) = __nv_bfloat162(h[2], h[3]);
    *reinterpret_cast<__nv_bfloat162*>(g_bf + loOff + i)     = __nv_bfloat162(l[0], l[1]);
    *reinterpret_cast<__nv_bfloat162*>(g_bf + loOff + i + 2) = __nv_bfloat162(l[2], l[3]);
}

// ---------------------------------------------------------------------------
// GEMM core: CTA tile 128x128, 256 threads, 2(M)x4(N) warps, warp tile 64x32.
// XOR-swizzled unpadded smem (8 KB/tile), 3-stage pipeline, 2 CTAs/SM.
// SINGLE barrier per k-tile: the top barrier at kt proves all warps finished
// reading stage (kt-1)%3, which is exactly the stage issue(kt+2) overwrites.
// wait(1) leaves only group kt+1 in flight.
// ---------------------------------------------------------------------------
#define NT 32
#define KT 32
#define TILEB 8192
#define STAGEB (4 * TILEB)        // 32768
#define GNSTG 3
#define GEMM_SMEM (GNSTG * STAGEB)  // 98304

// logical (row 0..127, chunk 0..3 of 16B) -> swizzled byte offset in tile
__device__ __forceinline__ uint32_t gsw(int r, int c) {
    uint32_t line = (uint32_t)(r >> 1);
    uint32_t cil  = ((uint32_t)(r & 1) << 2) | (uint32_t)c;
    return (line << 7) + ((cil ^ (line & 7)) << 4);
}

struct GemmAcc { float a[4][4][4]; };

__device__ __forceinline__ void gemm_core(
    uint32_t sbase, size_t aHi, size_t aLo, size_t bHi, size_t bLo,
    int m0, int n0, GemmAcc& A)
{
    const int tid  = threadIdx.x;
    const int lane = tid & 31;
    const int wid  = tid >> 5;

    const __nv_bfloat16* gp0 = g_bf + aHi + (size_t)m0 * 1024;
    const __nv_bfloat16* gp1 = g_bf + aLo + (size_t)m0 * 1024;
    const __nv_bfloat16* gp2 = g_bf + bHi + (size_t)n0 * 1024;
    const __nv_bfloat16* gp3 = g_bf + bLo + (size_t)n0 * 1024;

    auto issue = [&](int kt, int stage) {
        const int kc = kt * KT;
#pragma unroll
        for (int j = 0; j < 8; j++) {
            int c    = tid + j * 256;
            int tile = c >> 9;
            int w    = c & 511;
            int r    = w >> 2;
            int qq   = w & 3;
            uint32_t dst = sbase + stage * STAGEB + tile * TILEB + gsw(r, qq);
            const __nv_bfloat16* base =
                (tile == 0) ? gp0 : (tile == 1) ? gp1 : (tile == 2) ? gp2 : gp3;
            CP_ASYNC16(dst, base + (size_t)r * 1024 + kc + qq * 8);
        }
        CP_COMMIT();
    };

    issue(0, 0);
    issue(1, 1);

    const int wm = wid & 1;
    const int wn = wid >> 1;
    const int a_row = (lane & 7) + ((lane >> 3) & 1) * 8;
    const int a_chk = (lane >> 4);           // + ks*2
    const int b_row = (lane & 7) + ((lane >> 4)) * 8;
    const int b_chk = ((lane >> 3) & 1);     // + ks*2

#pragma unroll
    for (int i = 0; i < 4; i++)
#pragma unroll
        for (int j = 0; j < 4; j++)
#pragma unroll
            for (int e = 0; e < 4; e++) A.a[i][j][e] = 0.f;

    int stg = 0;        // kt % 3
    int stg2 = 2;       // (kt+2) % 3
    for (int kt = 0; kt < NT; kt++) {
        if (kt < NT - 1) CP_WAIT(1); else CP_WAIT(0);
        __syncthreads();    // all warps done reading stage (kt-1)%3 == stg2

        if (kt + 2 < NT) issue(kt + 2, stg2);

        const uint32_t st = sbase + stg * STAGEB;

#pragma unroll
        for (int ks = 0; ks < 2; ks++) {
            uint32_t bH[2][4], bL[2][4];
#pragma unroll
            for (int j = 0; j < 2; j++) {
                uint32_t bd = st + 2 * TILEB +
                              gsw(wn * 32 + j * 16 + b_row, ks * 2 + b_chk);
                LDSM4(bH[j], bd);
                LDSM4(bL[j], bd + TILEB);
            }
            // A in two halves: only 2 row-fragments (hi+lo) live at a time
#pragma unroll
            for (int ih = 0; ih < 2; ih++) {
                uint32_t aH[2][4], aL[2][4];
#pragma unroll
                for (int i = 0; i < 2; i++) {
                    uint32_t ad = st +
                        gsw(wm * 64 + (ih * 2 + i) * 16 + a_row, ks * 2 + a_chk);
                    LDSM4(aH[i], ad);
                    LDSM4(aL[i], ad + TILEB);
                }
#pragma unroll
                for (int i = 0; i < 2; i++) {
#pragma unroll
                    for (int jf = 0; jf < 4; jf++) {
                        uint32_t h0 = bH[jf >> 1][(jf & 1) * 2];
                        uint32_t h1 = bH[jf >> 1][(jf & 1) * 2 + 1];
                        uint32_t l0 = bL[jf >> 1][(jf & 1) * 2];
                        uint32_t l1 = bL[jf >> 1][(jf & 1) * 2 + 1];
                        float* acc = A.a[ih * 2 + i][jf];
                        MMA16816(acc, aH[i], h0, h1);
                        MMA16816(acc, aH[i], l0, l1);
                        MMA16816(acc, aL[i], h0, h1);
                    }
                }
            }
        }
        // no trailing barrier — next iteration's top barrier provides safety
        stg  = (stg == 2) ? 0 : stg + 1;
        stg2 = (stg2 == 2) ? 0 : stg2 + 1;
    }
    __syncthreads();    // protect smem reuse by epilogue staging (none) / exit
}

// QKV projections merged into one launch: blockIdx.z in {0,1,2}
__global__ __launch_bounds__(256, 2) void gemm_qkv(
    const float* __restrict__ bq, const float* __restrict__ bk,
    const float* __restrict__ bv)
{
    extern __shared__ char sm[];
    const uint32_t sbase = smem_u32(sm);
    const int lane = threadIdx.x & 31;
    const int wid  = threadIdx.x >> 5;
    const int m0 = blockIdx.y << 7;
    const int n0 = blockIdx.x << 7;
    const int z  = blockIdx.z;

    size_t aHi, aLo, bHi, bLo, dH, dL;
    const float* bias;
    if (z == 0) { aHi = OFF_XQ_HI; aLo = OFF_XQ_LO; bHi = OFF_WQ_HI; bLo = OFF_WQ_LO;
                  dH = OFF_AQ_HI; dL = OFF_AQ_LO; bias = bq; }
    else if (z == 1) { aHi = OFF_XK_HI; aLo = OFF_XK_LO; bHi = OFF_WK_HI; bLo = OFF_WK_LO;
                  dH = OFF_AK_HI; dL = OFF_AK_LO; bias = bk; }
    else { aHi = OFF_XV_HI; aLo = OFF_XV_LO; bHi = OFF_WV_HI; bLo = OFF_WV_LO;
                  dH = OFF_AV_HI; dL = OFF_AV_LO; bias = bv; }

    GemmAcc A;
    gemm_core(sbase, aHi, aLo, bHi, bLo, m0, n0, A);

    const int mrb = m0 + (wid & 1) * 64;
    const int ncb = n0 + (wid >> 1) * 32;
    __nv_bfloat16* hp = g_bf + dH;
    __nv_bfloat16* lp = g_bf + dL;
#pragma unroll
    for (int i = 0; i < 4; i++) {
        int r0 = mrb + i * 16 + (lane >> 2);
#pragma unroll
        for (int jf = 0; jf < 4; jf++) {
            int c = ncb + jf * 8 + (lane & 3) * 2;
            float bx = __ldg(bias + c);
            float by = __ldg(bias + c + 1);
            int h = c >> 6, d = c & 63;
            size_t ix0 = ((size_t)(((r0 >> 11) << 4) | h) << 17)
                       + ((size_t)(r0 & 2047) << 6) + d;
            split_store2(hp, lp, ix0, A.a[i][jf][0] + bx, A.a[i][jf][1] + by);
            split_store2(hp, lp, ix0 + (8ull << 6), A.a[i][jf][2] + bx, A.a[i][jf][3] + by);
        }
    }
}

// Output projection: ctx (split bf16) x Wo^T + bo -> fp32 out
__global__ __launch_bounds__(256, 2) void gemm_out(
    const float* __restrict__ bias, float* __restrict__ ext)
{
    extern __shared__ char sm[];
    const uint32_t sbase = smem_u32(sm);
    const int lane = threadIdx.x & 31;
    const int wid  = threadIdx.x >> 5;
    const int m0 = blockIdx.y << 7;
    const int n0 = blockIdx.x << 7;

    GemmAcc A;
    gemm_core(sbase, OFF_CTX_HI, OFF_CTX_LO, OFF_WO_HI, OFF_WO_LO, m0, n0, A);

    const int mrb = m0 + (wid & 1) * 64;
    const int ncb = n0 + (wid >> 1) * 32;
#pragma unroll
    for (int i = 0; i < 4; i++) {
        int r0 = mrb + i * 16 + (lane >> 2);
#pragma unroll
        for (int jf = 0; jf < 4; jf++) {
            int cb = ncb + jf * 8 + (lane & 3) * 2;
            float bx = __ldg(bias + cb);
            float by = __ldg(bias + cb + 1);
            float2 o0 = make_float2(A.a[i][jf][0] + bx, A.a[i][jf][1] + by);
            float2 o1 = make_float2(A.a[i][jf][2] + bx, A.a[i][jf][3] + by);
            *reinterpret_cast<float2*>(ext + (size_t)r0 * 1024 + cb)       = o0;
            *reinterpret_cast<float2*>(ext + (size_t)(r0 + 8) * 1024 + cb) = o1;
        }
    }
}

// ---------------------------------------------------------------------------
// Tensor-core flash attention (split-bf16, fixed-scale softmax).
// CTA: 128 queries x one (b,h). 8 warps x 16-q tiles. Key tiles of 64.
// 3-stage cp.async pipeline (wait ladder 2/1/0); unchanged from R13 (near floor).
// ---------------------------------------------------------------------------
#define ATT_STAGE 32768            // KH 8K | KL 8K | VH 8K | VL 8K
#define ATT_NSTG  3
#define ATT_SMEM  (ATT_NSTG * ATT_STAGE)  // 96 KB

__global__ __launch_bounds__(256, 2) void attn_tc()
{
    extern __shared__ char sm[];
    const uint32_t sb = smem_u32(sm);
    const int tid = threadIdx.x, lane = tid & 31, wid = tid >> 5;
    const int bh = blockIdx.y;
    const int q0 = blockIdx.x << 7;

    const __nv_bfloat16* Qh = g_bf + OFF_AQ_HI + ((size_t)bh << 17) + ((size_t)q0 << 6);
    const __nv_bfloat16* Ql = g_bf + OFF_AQ_LO + ((size_t)bh << 17) + ((size_t)q0 << 6);
    const __nv_bfloat16* Kh = g_bf + OFF_AK_HI + ((size_t)bh << 17);
    const __nv_bfloat16* Kl = g_bf + OFF_AK_LO + ((size_t)bh << 17);
    const __nv_bfloat16* Vh = g_bf + OFF_AV_HI + ((size_t)bh << 17);
    const __nv_bfloat16* Vl = g_bf + OFF_AV_LO + ((size_t)bh << 17);

    // ---- stage Q tile (128x64 hi+lo) into stage-0 smem, then to registers ----
#pragma unroll
    for (int j = 0; j < 8; j++) {
        int c = tid + j * 256;
        int t = c >> 10;
        int r = (c >> 3) & 127;
        int cb = c & 7;
        uint32_t dst = sb + t * 16384 + r * 128 + ((cb ^ (r & 7)) << 4);
        const __nv_bfloat16* src = (t ? Ql : Qh) + (size_t)r * 64 + cb * 8;
        CP_ASYNC16(dst, src);
    }
    CP_COMMIT(); CP_WAIT(0);
    __syncthreads();

    uint32_t aQh[4][4], aQl[4][4];
    {
        int row = (wid << 4) + (lane & 7) + ((lane >> 3) & 1) * 8;
#pragma unroll
        for (int ks = 0; ks < 4; ks++) {
            int cb = ks * 2 + (lane >> 4);
            uint32_t ad = sb + row * 128 + ((cb ^ (row & 7)) << 4);
            LDSM4(aQh[ks], ad);
            LDSM4(aQl[ks], ad + 16384);
        }
    }
    __syncthreads();

    // ---- KV pipeline ----
    auto issue = [&](int kt, int stg) {
        const int k0 = kt << 6;
#pragma unroll
        for (int j = 0; j < 8; j++) {
            int c = tid + j * 256;
            int t = c >> 9;
            int r = (c >> 3) & 63;
            int cb = c & 7;
            uint32_t dst = sb + stg * ATT_STAGE + t * 8192 + r * 128 + ((cb ^ (r & 7)) << 4);
            const __nv_bfloat16* base = (t == 0) ? Kh : (t == 1) ? Kl : (t == 2) ? Vh : Vl;
            CP_ASYNC16(dst, base + (size_t)(k0 + r) * 64 + cb * 8);
        }
        CP_COMMIT();
    };
    issue(0, 0);
    issue(1, 1);
    issue(2, 2);

    float O[8][4];
#pragma unroll
    for (int f = 0; f < 8; f++)
#pragma unroll
        for (int e = 0; e < 4; e++) O[f][e] = 0.f;
    float l0 = 0.f, l1 = 0.f;
    const float cs = 0.125f * 1.4426950408889634f;

    const int krow = (lane & 7) + (lane >> 4) * 8;
    const int kcb  = (lane >> 3) & 1;
    const int vrow = (lane & 7) + ((lane >> 3) & 1) * 8;
    const int vcb  = lane >> 4;

    int stg = 0;  // kt % 3
    for (int kt = 0; kt < 32; kt++) {
        if (kt < 30) CP_WAIT(2);
        else if (kt == 30) CP_WAIT(1);
        else CP_WAIT(0);
        __syncthreads();
        const uint32_t st = sb + stg * ATT_STAGE;

        // two key-halves of 32 keys each: compute S-half, softmax, PV-half
#pragma unroll
        for (int h2 = 0; h2 < 2; h2++) {
            float S[4][4];
#pragma unroll
            for (int f = 0; f < 4; f++)
#pragma unroll
                for (int e = 0; e < 4; e++) S[f][e] = 0.f;

#pragma unroll
            for (int ks = 0; ks < 4; ks++) {
#pragma unroll
                for (int gg = 0; gg < 2; gg++) {
                    int g = 2 * h2 + gg;
                    int rr = g * 16 + krow;
                    int cb = ks * 2 + kcb;
                    uint32_t ad = st + rr * 128 + ((cb ^ (rr & 7)) << 4);
                    uint32_t KH[4], KL[4];
                    LDSM4(KH, ad);
                    LDSM4(KL, ad + 8192);
                    MMA16816(S[2 * gg],     aQh[ks], KH[0], KH[1]);
                    MMA16816(S[2 * gg],     aQh[ks], KL[0], KL[1]);
                    MMA16816(S[2 * gg],     aQl[ks], KH[0], KH[1]);
                    MMA16816(S[2 * gg + 1], aQh[ks], KH[2], KH[3]);
                    MMA16816(S[2 * gg + 1], aQh[ks], KL[2], KL[3]);
                    MMA16816(S[2 * gg + 1], aQl[ks], KH[2], KH[3]);
                }
            }

#pragma unroll
            for (int f = 0; f < 4; f++) {
#pragma unroll
                for (int e = 0; e < 4; e++) S[f][e] = ex2(S[f][e] * cs);
                l0 += S[f][0] + S[f][1];
                l1 += S[f][2] + S[f][3];
            }

#pragma unroll
            for (int jj = 0; jj < 2; jj++) {
                int kk = 2 * h2 + jj;
                uint32_t pH[4], pL[4];
                float* Sa = S[2 * jj];
                float* Sb = S[2 * jj + 1];
                pH[0] = packbf(Sa[0], Sa[1]);
                pH[1] = packbf(Sa[2], Sa[3]);
                pH[2] = packbf(Sb[0], Sb[1]);
                pH[3] = packbf(Sb[2], Sb[3]);
                pL[0] = packbf(Sa[0] - bflo(pH[0]), Sa[1] - bfhi(pH[0]));
                pL[1] = packbf(Sa[2] - bflo(pH[1]), Sa[3] - bfhi(pH[1]));
                pL[2] = packbf(Sb[0] - bflo(pH[2]), Sb[1] - bfhi(pH[2]));
                pL[3] = packbf(Sb[2] - bflo(pH[3]), Sb[3] - bfhi(pH[3]));
#pragma unroll
                for (int dp = 0; dp < 4; dp++) {
                    int rr = kk * 16 + vrow;
                    int cb = dp * 2 + vcb;
                    uint32_t ad = st + 16384 + rr * 128 + ((cb ^ (rr & 7)) << 4);
                    uint32_t VH[4], VL[4];
                    LDSM4T(VH, ad);
                    LDSM4T(VL, ad + 8192);
                    MMA16816(O[2 * dp],     pH, VH[0], VH[1]);
                    MMA16816(O[2 * dp],     pH, VL[0], VL[1]);
                    MMA16816(O[2 * dp],     pL, VH[0], VH[1]);
                    MMA16816(O[2 * dp + 1], pH, VH[2], VH[3]);
                    MMA16816(O[2 * dp + 1], pH, VL[2], VL[3]);
                    MMA16816(O[2 * dp + 1], pL, VH[2], VH[3]);
                }
            }
        }

        __syncthreads();
        if (kt + 3 < 32) issue(kt + 3, stg);   // tile kt+3 reuses stage kt%3
        stg = (stg == 2) ? 0 : stg + 1;
    }

    // ---- epilogue: normalize and write ctx as bf16 hi/lo [b,s,1024] ----
    l0 += __shfl_xor_sync(0xffffffffu, l0, 1);
    l0 += __shfl_xor_sync(0xffffffffu, l0, 2);
    l1 += __shfl_xor_sync(0xffffffffu, l1, 1);
    l1 += __shfl_xor_sync(0xffffffffu, l1, 2);
    const float inv0 = 1.f / l0;
    const float inv1 = 1.f / l1;

    const int b = bh >> 4, h = bh & 15;
    const int r0g = b * 2048 + q0 + (wid << 4) + (lane >> 2);
    __nv_bfloat16* ch = g_bf + OFF_CTX_HI;
    __nv_bfloat16* cl = g_bf + OFF_CTX_LO;
#pragma unroll
    for (int f = 0; f < 8; f++) {
        int col = (h << 6) + f * 8 + (lane & 3) * 2;
        split_store2(ch, cl, (size_t)r0g * 1024 + col,
                     O[f][0] * inv0, O[f][1] * inv0);
        split_store2(ch, cl, (size_t)(r0g + 8) * 1024 + col,
                     O[f][2] * inv1, O[f][3] * inv1);
    }
}

// ---------------------------------------------------------------------------
extern "C" void kernel_launch(void* const* d_in, const int* in_sizes, int n_in,
                              void* d_out, int out_size)
{
    const float* query = (const float*)d_in[0];
    const float* key   = (const float*)d_in[1];
    const float* value = (const float*)d_in[2];
    const float* Wq = (const float*)d_in[3];
    const float* bq = (const float*)d_in[4];
    const float* Wk = (const float*)d_in[5];
    const float* bk = (const float*)d_in[6];
    const float* Wv = (const float*)d_in[7];
    const float* bv = (const float*)d_in[8];
    const float* Wo = (const float*)d_in[9];
    const float* bo = (const float*)d_in[10];
    float* out = (float*)d_out;

    cudaFuncSetAttribute(gemm_qkv, cudaFuncAttributeMaxDynamicSharedMemorySize, GEMM_SMEM);
    cudaFuncSetAttribute(gemm_out, cudaFuncAttributeMaxDynamicSharedMemorySize, GEMM_SMEM);
    cudaFuncSetAttribute(attn_tc,  cudaFuncAttributeMaxDynamicSharedMemorySize, ATT_SMEM);

    convert_all<<<16384, 256>>>(query, key, value, Wq, Wk, Wv, Wo);

    gemm_qkv<<<dim3(DM / 128, MROWS / 128, 3), 256, GEMM_SMEM>>>(bq, bk, bv);

    attn_tc<<<dim3(SEQ / 128, BATCH * NH), 256, ATT_SMEM>>>();

    gemm_out<<<dim3(DM / 128, MROWS / 128), 256, GEMM_SMEM>>>(bo, out);
}

// round 16
// speedup vs baseline: 1.3832x; 1.1852x over previous
#include <cuda_runtime.h>
#include <cuda_bf16.h>
#include <cuda_fp16.h>
#include <cstdint>
#include <cstddef>

// Problem constants: B=2, S=2048, D_MODEL=1024, H=16, d_k=64
#define BATCH 2
#define SEQ 2048
#define DM 1024
#define NH 16
#define MROWS (BATCH * SEQ)   // 4096

// ---------------------------------------------------------------------------
// bf16 pool (element offsets). AV region holds fp16 V (same 2B elements).
// ---------------------------------------------------------------------------
#define SZ_ACT (4096ull * 1024ull)
#define SZ_W   (1024ull * 1024ull)
#define OFF_XQ_HI 0ull
#define OFF_XQ_LO (OFF_XQ_HI + SZ_ACT)
#define OFF_XK_HI (OFF_XQ_LO + SZ_ACT)
#define OFF_XK_LO (OFF_XK_HI + SZ_ACT)
#define OFF_XV_HI (OFF_XK_LO + SZ_ACT)
#define OFF_XV_LO (OFF_XV_HI + SZ_ACT)
#define OFF_WQ_HI (OFF_XV_LO + SZ_ACT)
#define OFF_WQ_LO (OFF_WQ_HI + SZ_W)
#define OFF_WK_HI (OFF_WQ_LO + SZ_W)
#define OFF_WK_LO (OFF_WK_HI + SZ_W)
#define OFF_WV_HI (OFF_WK_LO + SZ_W)
#define OFF_WV_LO (OFF_WV_HI + SZ_W)
#define OFF_WO_HI (OFF_WV_LO + SZ_W)
#define OFF_WO_LO (OFF_WO_HI + SZ_W)
#define OFF_CTX_HI (OFF_WO_LO + SZ_W)
#define OFF_CTX_LO (OFF_CTX_HI + SZ_ACT)
// head-major attention operands: [b*16+h][s][64]
#define OFF_AQ_HI (OFF_CTX_LO + SZ_ACT)
#define OFF_AQ_LO (OFF_AQ_HI + SZ_ACT)
#define OFF_AK_HI (OFF_AQ_LO + SZ_ACT)
#define OFF_AK_LO (OFF_AK_HI + SZ_ACT)
#define OFF_AVF   (OFF_AK_LO + SZ_ACT)    // V as fp16 (raw 2-byte slots)
#define BF_TOTAL  (OFF_AVF + SZ_ACT)
__device__ __nv_bfloat16 g_bf[BF_TOTAL];

// ---------------------------------------------------------------------------
// PTX helpers — baseline ISA only (cp.async / ldmatrix / mma.sync / cvt)
// ---------------------------------------------------------------------------
__device__ __forceinline__ uint32_t smem_u32(const void* p) {
    uint32_t a;
    asm("{ .reg .u64 t; cvta.to.shared.u64 t, %1; cvt.u32.u64 %0, t; }"
        : "=r"(a) : "l"(p));
    return a;
}

#define CP_ASYNC16(dst, src) \
    asm volatile("cp.async.cg.shared.global [%0], [%1], 16;" :: "r"(dst), "l"(src))
#define CP_COMMIT() asm volatile("cp.async.commit_group;" ::: "memory")
#define CP_WAIT(N)  asm volatile("cp.async.wait_group %0;" :: "n"(N) : "memory")

#define LDSM4(R, addr) \
    asm volatile("ldmatrix.sync.aligned.m8n8.x4.shared.b16 {%0,%1,%2,%3}, [%4];" \
        : "=r"((R)[0]), "=r"((R)[1]), "=r"((R)[2]), "=r"((R)[3]) : "r"(addr))
#define LDSM4T(R, addr) \
    asm volatile("ldmatrix.sync.aligned.m8n8.x4.trans.shared.b16 {%0,%1,%2,%3}, [%4];" \
        : "=r"((R)[0]), "=r"((R)[1]), "=r"((R)[2]), "=r"((R)[3]) : "r"(addr))

#define MMA16816(C, A, b0, b1) \
    asm volatile("mma.sync.aligned.m16n8k16.row.col.f32.bf16.bf16.f32 " \
        "{%0,%1,%2,%3}, {%4,%5,%6,%7}, {%8,%9}, {%0,%1,%2,%3};" \
        : "+f"((C)[0]), "+f"((C)[1]), "+f"((C)[2]), "+f"((C)[3]) \
        : "r"((A)[0]), "r"((A)[1]), "r"((A)[2]), "r"((A)[3]), "r"(b0), "r"(b1))

#define MMAF16(C, A, b0, b1) \
    asm volatile("mma.sync.aligned.m16n8k16.row.col.f32.f16.f16.f32 " \
        "{%0,%1,%2,%3}, {%4,%5,%6,%7}, {%8,%9}, {%0,%1,%2,%3};" \
        : "+f"((C)[0]), "+f"((C)[1]), "+f"((C)[2]), "+f"((C)[3]) \
        : "r"((A)[0]), "r"((A)[1]), "r"((A)[2]), "r"((A)[3]), "r"(b0), "r"(b1))

__device__ __forceinline__ float ex2(float x) {
    float r; asm("ex2.approx.ftz.f32 %0, %1;" : "=f"(r) : "f"(x)); return r;
}
__device__ __forceinline__ uint32_t packbf(float lo, float hi) {
    uint32_t u;
    asm("cvt.rn.bf16x2.f32 %0, %1, %2;" : "=r"(u) : "f"(hi), "f"(lo));
    return u;
}
__device__ __forceinline__ float bflo(uint32_t u) { return __uint_as_float(u << 16); }
__device__ __forceinline__ float bfhi(uint32_t u) { return __uint_as_float(u & 0xffff0000u); }
__device__ __forceinline__ uint32_t packh(float lo, float hi) {
    __half2 h = __floats2half2_rn(lo, hi);
    return *reinterpret_cast<uint32_t*>(&h);
}

__device__ __forceinline__ void split_store2(
    __nv_bfloat16* hp, __nv_bfloat16* lp, size_t idx, float a, float b)
{
    __nv_bfloat16 ha = __float2bfloat16(a);
    __nv_bfloat16 hb = __float2bfloat16(b);
    __nv_bfloat16 la = __float2bfloat16(a - __bfloat162float(ha));
    __nv_bfloat16 lb = __float2bfloat16(b - __bfloat162float(hb));
    *reinterpret_cast<__nv_bfloat162*>(hp + idx) = __nv_bfloat162(ha, hb);
    *reinterpret_cast<__nv_bfloat162*>(lp + idx) = __nv_bfloat162(la, lb);
}

// ---------------------------------------------------------------------------
// ONE merged fp32 -> bf16 hi/lo split conversion, 8 elements/thread,
// 16B vector stores. Blocks of 2048 elements:
//   [0,6144) x tensors (2048 blocks each), [6144,8192) weights (512 each)
// ---------------------------------------------------------------------------
__global__ __launch_bounds__(256) void convert_all(
    const float* __restrict__ q, const float* __restrict__ k,
    const float* __restrict__ v, const float* __restrict__ wq,
    const float* __restrict__ wk, const float* __restrict__ wv,
    const float* __restrict__ wo)
{
    const int blk = blockIdx.x;
    const float* src;
    size_t hiOff, loOff, base;
    if (blk < 6144) {
        int t = blk >> 11;
        src = (t == 0) ? q : (t == 1) ? k : v;
        hiOff = (t == 0) ? OFF_XQ_HI : (t == 1) ? OFF_XK_HI : OFF_XV_HI;
        loOff = (t == 0) ? OFF_XQ_LO : (t == 1) ? OFF_XK_LO : OFF_XV_LO;
        base = ((size_t)(blk & 2047)) << 11;
    } else {
        int b2 = blk - 6144;
        int t = b2 >> 9;
        src = (t == 0) ? wq : (t == 1) ? wk : (t == 2) ? wv : wo;
        hiOff = (t == 0) ? OFF_WQ_HI : (t == 1) ? OFF_WK_HI
              : (t == 2) ? OFF_WV_HI : OFF_WO_HI;
        loOff = (t == 0) ? OFF_WQ_LO : (t == 1) ? OFF_WK_LO
              : (t == 2) ? OFF_WV_LO : OFF_WO_LO;
        base = ((size_t)(b2 & 511)) << 11;
    }
    size_t i = base + (size_t)threadIdx.x * 8;
    float4 x0 = *(const float4*)(src + i);
    float4 x1 = *(const float4*)(src + i + 4);
    float vv[8] = {x0.x, x0.y, x0.z, x0.w, x1.x, x1.y, x1.z, x1.w};
    uint32_t hp[4], lp[4];
#pragma unroll
    for (int p = 0; p < 4; p++) {
        float a = vv[2 * p], b = vv[2 * p + 1];
        uint32_t hh = packbf(a, b);
        lp[p] = packbf(a - bflo(hh), b - bfhi(hh));
        hp[p] = hh;
    }
    *reinterpret_cast<uint4*>(g_bf + hiOff + i) = make_uint4(hp[0], hp[1], hp[2], hp[3]);
    *reinterpret_cast<uint4*>(g_bf + loOff + i) = make_uint4(lp[0], lp[1], lp[2], lp[3]);
}

// ---------------------------------------------------------------------------
// GEMM core: CTA tile 128x128, 256 threads, 2(M)x4(N) warps, warp tile 64x32.
// XOR-swizzled unpadded smem (8 KB/tile), 3-stage pipeline, single barrier
// per k-tile (R15-proven), 2 CTAs/SM.
// ---------------------------------------------------------------------------
#define NT 32
#define KT 32
#define TILEB 8192
#define STAGEB (4 * TILEB)        // 32768
#define GNSTG 3
#define GEMM_SMEM (GNSTG * STAGEB)  // 98304

__device__ __forceinline__ uint32_t gsw(int r, int c) {
    uint32_t line = (uint32_t)(r >> 1);
    uint32_t cil  = ((uint32_t)(r & 1) << 2) | (uint32_t)c;
    return (line << 7) + ((cil ^ (line & 7)) << 4);
}

struct GemmAcc { float a[4][4][4]; };

__device__ __forceinline__ void gemm_core(
    uint32_t sbase, size_t aHi, size_t aLo, size_t bHi, size_t bLo,
    int m0, int n0, GemmAcc& A)
{
    const int tid  = threadIdx.x;
    const int lane = tid & 31;
    const int wid  = tid >> 5;

    const __nv_bfloat16* gp0 = g_bf + aHi + (size_t)m0 * 1024;
    const __nv_bfloat16* gp1 = g_bf + aLo + (size_t)m0 * 1024;
    const __nv_bfloat16* gp2 = g_bf + bHi + (size_t)n0 * 1024;
    const __nv_bfloat16* gp3 = g_bf + bLo + (size_t)n0 * 1024;

    auto issue = [&](int kt, int stage) {
        const int kc = kt * KT;
#pragma unroll
        for (int j = 0; j < 8; j++) {
            int c    = tid + j * 256;
            int tile = c >> 9;
            int w    = c & 511;
            int r    = w >> 2;
            int qq   = w & 3;
            uint32_t dst = sbase + stage * STAGEB + tile * TILEB + gsw(r, qq);
            const __nv_bfloat16* base =
                (tile == 0) ? gp0 : (tile == 1) ? gp1 : (tile == 2) ? gp2 : gp3;
            CP_ASYNC16(dst, base + (size_t)r * 1024 + kc + qq * 8);
        }
        CP_COMMIT();
    };

    issue(0, 0);
    issue(1, 1);

    const int wm = wid & 1;
    const int wn = wid >> 1;
    const int a_row = (lane & 7) + ((lane >> 3) & 1) * 8;
    const int a_chk = (lane >> 4);
    const int b_row = (lane & 7) + ((lane >> 4)) * 8;
    const int b_chk = ((lane >> 3) & 1);

#pragma unroll
    for (int i = 0; i < 4; i++)
#pragma unroll
        for (int j = 0; j < 4; j++)
#pragma unroll
            for (int e = 0; e < 4; e++) A.a[i][j][e] = 0.f;

    int stg = 0;        // kt % 3
    int stg2 = 2;       // (kt+2) % 3
    for (int kt = 0; kt < NT; kt++) {
        if (kt < NT - 1) CP_WAIT(1); else CP_WAIT(0);
        __syncthreads();    // all warps done reading stage (kt-1)%3 == stg2

        if (kt + 2 < NT) issue(kt + 2, stg2);

        const uint32_t st = sbase + stg * STAGEB;

#pragma unroll
        for (int ks = 0; ks < 2; ks++) {
            uint32_t bH[2][4], bL[2][4];
#pragma unroll
            for (int j = 0; j < 2; j++) {
                uint32_t bd = st + 2 * TILEB +
                              gsw(wn * 32 + j * 16 + b_row, ks * 2 + b_chk);
                LDSM4(bH[j], bd);
                LDSM4(bL[j], bd + TILEB);
            }
#pragma unroll
            for (int ih = 0; ih < 2; ih++) {
                uint32_t aH[2][4], aL[2][4];
#pragma unroll
                for (int i = 0; i < 2; i++) {
                    uint32_t ad = st +
                        gsw(wm * 64 + (ih * 2 + i) * 16 + a_row, ks * 2 + a_chk);
                    LDSM4(aH[i], ad);
                    LDSM4(aL[i], ad + TILEB);
                }
#pragma unroll
                for (int i = 0; i < 2; i++) {
#pragma unroll
                    for (int jf = 0; jf < 4; jf++) {
                        uint32_t h0 = bH[jf >> 1][(jf & 1) * 2];
                        uint32_t h1 = bH[jf >> 1][(jf & 1) * 2 + 1];
                        uint32_t l0 = bL[jf >> 1][(jf & 1) * 2];
                        uint32_t l1 = bL[jf >> 1][(jf & 1) * 2 + 1];
                        float* acc = A.a[ih * 2 + i][jf];
                        MMA16816(acc, aH[i], h0, h1);
                        MMA16816(acc, aH[i], l0, l1);
                        MMA16816(acc, aL[i], h0, h1);
                    }
                }
            }
        }
        stg  = (stg == 2) ? 0 : stg + 1;
        stg2 = (stg2 == 2) ? 0 : stg2 + 1;
    }
    __syncthreads();
}

// QKV projections merged into one launch: blockIdx.z in {0,1,2}
// All 3-term. Q/K write bf16 hi/lo; V writes fp16 single.
__global__ __launch_bounds__(256, 2) void gemm_qkv(
    const float* __restrict__ bq, const float* __restrict__ bk,
    const float* __restrict__ bv)
{
    extern __shared__ char sm[];
    const uint32_t sbase = smem_u32(sm);
    const int lane = threadIdx.x & 31;
    const int wid  = threadIdx.x >> 5;
    const int m0 = blockIdx.y << 7;
    const int n0 = blockIdx.x << 7;
    const int z  = blockIdx.z;

    size_t aHi, aLo, bHi, bLo;
    const float* bias;
    if (z == 0) { aHi = OFF_XQ_HI; aLo = OFF_XQ_LO; bHi = OFF_WQ_HI; bLo = OFF_WQ_LO; bias = bq; }
    else if (z == 1) { aHi = OFF_XK_HI; aLo = OFF_XK_LO; bHi = OFF_WK_HI; bLo = OFF_WK_LO; bias = bk; }
    else { aHi = OFF_XV_HI; aLo = OFF_XV_LO; bHi = OFF_WV_HI; bLo = OFF_WV_LO; bias = bv; }

    GemmAcc A;
    gemm_core(sbase, aHi, aLo, bHi, bLo, m0, n0, A);

    const int mrb = m0 + (wid & 1) * 64;
    const int ncb = n0 + (wid >> 1) * 32;
#pragma unroll
    for (int i = 0; i < 4; i++) {
        int r0 = mrb + i * 16 + (lane >> 2);
#pragma unroll
        for (int jf = 0; jf < 4; jf++) {
            int c = ncb + jf * 8 + (lane & 3) * 2;
            float bx = __ldg(bias + c);
            float by = __ldg(bias + c + 1);
            int h = c >> 6, d = c & 63;
            size_t ix0 = ((size_t)(((r0 >> 11) << 4) | h) << 17)
                       + ((size_t)(r0 & 2047) << 6) + d;
            float v00 = A.a[i][jf][0] + bx, v01 = A.a[i][jf][1] + by;
            float v10 = A.a[i][jf][2] + bx, v11 = A.a[i][jf][3] + by;
            if (z == 2) {
                // V: fp16 single precision (feeds fp16 PV MMA)
                *reinterpret_cast<uint32_t*>(g_bf + OFF_AVF + ix0) = packh(v00, v01);
                *reinterpret_cast<uint32_t*>(g_bf + OFF_AVF + ix0 + (8ull << 6)) = packh(v10, v11);
            } else {
                __nv_bfloat16* hp = g_bf + (z == 0 ? OFF_AQ_HI : OFF_AK_HI);
                __nv_bfloat16* lp = g_bf + (z == 0 ? OFF_AQ_LO : OFF_AK_LO);
                split_store2(hp, lp, ix0, v00, v01);
                split_store2(hp, lp, ix0 + (8ull << 6), v10, v11);
            }
        }
    }
}

// Output projection: ctx (split bf16) x Wo^T + bo -> fp32 out (3-term)
__global__ __launch_bounds__(256, 2) void gemm_out(
    const float* __restrict__ bias, float* __restrict__ ext)
{
    extern __shared__ char sm[];
    const uint32_t sbase = smem_u32(sm);
    const int lane = threadIdx.x & 31;
    const int wid  = threadIdx.x >> 5;
    const int m0 = blockIdx.y << 7;
    const int n0 = blockIdx.x << 7;

    GemmAcc A;
    gemm_core(sbase, OFF_CTX_HI, OFF_CTX_LO, OFF_WO_HI, OFF_WO_LO, m0, n0, A);

    const int mrb = m0 + (wid & 1) * 64;
    const int ncb = n0 + (wid >> 1) * 32;
#pragma unroll
    for (int i = 0; i < 4; i++) {
        int r0 = mrb + i * 16 + (lane >> 2);
#pragma unroll
        for (int jf = 0; jf < 4; jf++) {
            int cb = ncb + jf * 8 + (lane & 3) * 2;
            float bx = __ldg(bias + cb);
            float by = __ldg(bias + cb + 1);
            float2 o0 = make_float2(A.a[i][jf][0] + bx, A.a[i][jf][1] + by);
            float2 o1 = make_float2(A.a[i][jf][2] + bx, A.a[i][jf][3] + by);
            *reinterpret_cast<float2*>(ext + (size_t)r0 * 1024 + cb)       = o0;
            *reinterpret_cast<float2*>(ext + (size_t)(r0 + 8) * 1024 + cb) = o1;
        }
    }
}

// ---------------------------------------------------------------------------
// Tensor-core flash attention. QK^T bf16 3-term; PV fp16 SINGLE term.
// CTA: 128 queries x one (b,h). 8 warps x 16-q tiles. Key tiles of 64.
// Stage = KH 8K | KL 8K | Vf 8K = 24 KB; 3 stages; 2 CTAs/SM.
// ---------------------------------------------------------------------------
#define ATT_STAGE 24576
#define ATT_NSTG  3
#define ATT_SMEM  (ATT_NSTG * ATT_STAGE)  // 73728

__global__ __launch_bounds__(256, 2) void attn_tc()
{
    extern __shared__ char sm[];
    const uint32_t sb = smem_u32(sm);
    const int tid = threadIdx.x, lane = tid & 31, wid = tid >> 5;
    const int bh = blockIdx.y;
    const int q0 = blockIdx.x << 7;

    const __nv_bfloat16* Qh = g_bf + OFF_AQ_HI + ((size_t)bh << 17) + ((size_t)q0 << 6);
    const __nv_bfloat16* Ql = g_bf + OFF_AQ_LO + ((size_t)bh << 17) + ((size_t)q0 << 6);
    const __nv_bfloat16* Kh = g_bf + OFF_AK_HI + ((size_t)bh << 17);
    const __nv_bfloat16* Kl = g_bf + OFF_AK_LO + ((size_t)bh << 17);
    const __nv_bfloat16* Vf = g_bf + OFF_AVF   + ((size_t)bh << 17);

    // ---- stage Q tile (128x64 hi+lo) into smem, then to registers ----
#pragma unroll
    for (int j = 0; j < 8; j++) {
        int c = tid + j * 256;
        int t = c >> 10;
        int r = (c >> 3) & 127;
        int cb = c & 7;
        uint32_t dst = sb + t * 16384 + r * 128 + ((cb ^ (r & 7)) << 4);
        const __nv_bfloat16* src = (t ? Ql : Qh) + (size_t)r * 64 + cb * 8;
        CP_ASYNC16(dst, src);
    }
    CP_COMMIT(); CP_WAIT(0);
    __syncthreads();

    uint32_t aQh[4][4], aQl[4][4];
    {
        int row = (wid << 4) + (lane & 7) + ((lane >> 3) & 1) * 8;
#pragma unroll
        for (int ks = 0; ks < 4; ks++) {
            int cb = ks * 2 + (lane >> 4);
            uint32_t ad = sb + row * 128 + ((cb ^ (row & 7)) << 4);
            LDSM4(aQh[ks], ad);
            LDSM4(aQl[ks], ad + 16384);
        }
    }
    __syncthreads();

    // ---- KV pipeline: stage = KH | KL | Vf, 1536 chunks -> 6 per thread ----
    auto issue = [&](int kt, int stg) {
        const int k0 = kt << 6;
#pragma unroll
        for (int j = 0; j < 6; j++) {
            int c = tid + j * 256;
            int t = c >> 9;              // 0 KH, 1 KL, 2 Vf
            int r = (c >> 3) & 63;
            int cb = c & 7;
            uint32_t dst = sb + stg * ATT_STAGE + t * 8192 + r * 128 + ((cb ^ (r & 7)) << 4);
            const __nv_bfloat16* base = (t == 0) ? Kh : (t == 1) ? Kl : Vf;
            CP_ASYNC16(dst, base + (size_t)(k0 + r) * 64 + cb * 8);
        }
        CP_COMMIT();
    };
    issue(0, 0);
    issue(1, 1);
    issue(2, 2);

    float O[8][4];
#pragma unroll
    for (int f = 0; f < 8; f++)
#pragma unroll
        for (int e = 0; e < 4; e++) O[f][e] = 0.f;
    float l0 = 0.f, l1 = 0.f;
    const float cs = 0.125f * 1.4426950408889634f;

    const int krow = (lane & 7) + (lane >> 4) * 8;
    const int kcb  = (lane >> 3) & 1;
    const int vrow = (lane & 7) + ((lane >> 3) & 1) * 8;
    const int vcb  = lane >> 4;

    int stg = 0;  // kt % 3
    for (int kt = 0; kt < 32; kt++) {
        if (kt < 30) CP_WAIT(2);
        else if (kt == 30) CP_WAIT(1);
        else CP_WAIT(0);
        __syncthreads();
        const uint32_t st = sb + stg * ATT_STAGE;

        // two key-halves of 32 keys each: compute S-half, softmax, PV-half
#pragma unroll
        for (int h2 = 0; h2 < 2; h2++) {
            float S[4][4];
#pragma unroll
            for (int f = 0; f < 4; f++)
#pragma unroll
                for (int e = 0; e < 4; e++) S[f][e] = 0.f;

            // S = Q K^T, bf16 3-term
#pragma unroll
            for (int ks = 0; ks < 4; ks++) {
#pragma unroll
                for (int gg = 0; gg < 2; gg++) {
                    int g = 2 * h2 + gg;
                    int rr = g * 16 + krow;
                    int cb = ks * 2 + kcb;
                    uint32_t ad = st + rr * 128 + ((cb ^ (rr & 7)) << 4);
                    uint32_t KH[4], KL[4];
                    LDSM4(KH, ad);
                    LDSM4(KL, ad + 8192);
                    MMA16816(S[2 * gg],     aQh[ks], KH[0], KH[1]);
                    MMA16816(S[2 * gg],     aQh[ks], KL[0], KL[1]);
                    MMA16816(S[2 * gg],     aQl[ks], KH[0], KH[1]);
                    MMA16816(S[2 * gg + 1], aQh[ks], KH[2], KH[3]);
                    MMA16816(S[2 * gg + 1], aQh[ks], KL[2], KL[3]);
                    MMA16816(S[2 * gg + 1], aQl[ks], KH[2], KH[3]);
                }
            }

#pragma unroll
            for (int f = 0; f < 4; f++) {
#pragma unroll
                for (int e = 0; e < 4; e++) S[f][e] = ex2(S[f][e] * cs);
                l0 += S[f][0] + S[f][1];
                l1 += S[f][2] + S[f][3];
            }

            // O += P V, fp16 single term (P in fp16, V in fp16)
#pragma unroll
            for (int jj = 0; jj < 2; jj++) {
                int kk = 2 * h2 + jj;
                uint32_t pF[4];
                float* Sa = S[2 * jj];
                float* Sb = S[2 * jj + 1];
                pF[0] = packh(Sa[0], Sa[1]);
                pF[1] = packh(Sa[2], Sa[3]);
                pF[2] = packh(Sb[0], Sb[1]);
                pF[3] = packh(Sb[2], Sb[3]);
#pragma unroll
                for (int dp = 0; dp < 4; dp++) {
                    int rr = kk * 16 + vrow;
                    int cb = dp * 2 + vcb;
                    uint32_t ad = st + 16384 + rr * 128 + ((cb ^ (rr & 7)) << 4);
                    uint32_t VF[4];
                    LDSM4T(VF, ad);
                    MMAF16(O[2 * dp],     pF, VF[0], VF[1]);
                    MMAF16(O[2 * dp + 1], pF, VF[2], VF[3]);
                }
            }
        }

        __syncthreads();
        if (kt + 3 < 32) issue(kt + 3, stg);   // tile kt+3 reuses stage kt%3
        stg = (stg == 2) ? 0 : stg + 1;
    }

    // ---- epilogue: normalize and write ctx as bf16 hi/lo [b,s,1024] ----
    l0 += __shfl_xor_sync(0xffffffffu, l0, 1);
    l0 += __shfl_xor_sync(0xffffffffu, l0, 2);
    l1 += __shfl_xor_sync(0xffffffffu, l1, 1);
    l1 += __shfl_xor_sync(0xffffffffu, l1, 2);
    const float inv0 = 1.f / l0;
    const float inv1 = 1.f / l1;

    const int b = bh >> 4, h = bh & 15;
    const int r0g = b * 2048 + q0 + (wid << 4) + (lane >> 2);
    __nv_bfloat16* ch = g_bf + OFF_CTX_HI;
    __nv_bfloat16* cl = g_bf + OFF_CTX_LO;
#pragma unroll
    for (int f = 0; f < 8; f++) {
        int col = (h << 6) + f * 8 + (lane & 3) * 2;
        split_store2(ch, cl, (size_t)r0g * 1024 + col,
                     O[f][0] * inv0, O[f][1] * inv0);
        split_store2(ch, cl, (size_t)(r0g + 8) * 1024 + col,
                     O[f][2] * inv1, O[f][3] * inv1);
    }
}

// ---------------------------------------------------------------------------
extern "C" void kernel_launch(void* const* d_in, const int* in_sizes, int n_in,
                              void* d_out, int out_size)
{
    const float* query = (const float*)d_in[0];
    const float* key   = (const float*)d_in[1];
    const float* value = (const float*)d_in[2];
    const float* Wq = (const float*)d_in[3];
    const float* bq = (const float*)d_in[4];
    const float* Wk = (const float*)d_in[5];
    const float* bk = (const float*)d_in[6];
    const float* Wv = (const float*)d_in[7];
    const float* bv = (const float*)d_in[8];
    const float* Wo = (const float*)d_in[9];
    const float* bo = (const float*)d_in[10];
    float* out = (float*)d_out;

    cudaFuncSetAttribute(gemm_qkv, cudaFuncAttributeMaxDynamicSharedMemorySize, GEMM_SMEM);
    cudaFuncSetAttribute(gemm_out, cudaFuncAttributeMaxDynamicSharedMemorySize, GEMM_SMEM);
    cudaFuncSetAttribute(attn_tc,  cudaFuncAttributeMaxDynamicSharedMemorySize, ATT_SMEM);

    convert_all<<<8192, 256>>>(query, key, value, Wq, Wk, Wv, Wo);

    gemm_qkv<<<dim3(DM / 128, MROWS / 128, 3), 256, GEMM_SMEM>>>(bq, bk, bv);

    attn_tc<<<dim3(SEQ / 128, BATCH * NH), 256, ATT_SMEM>>>();

    gemm_out<<<dim3(DM / 128, MROWS / 128), 256, GEMM_SMEM>>>(bo, out);
}

// round 17
// speedup vs baseline: 1.8429x; 1.3323x over previous
#include <cuda_runtime.h>
#include <cuda_bf16.h>
#include <cuda_fp16.h>
#include <cstdint>
#include <cstddef>

// Problem constants: B=2, S=2048, D_MODEL=1024, H=16, d_k=64
#define BATCH 2
#define SEQ 2048
#define DM 1024
#define NH 16
#define MROWS (BATCH * SEQ)   // 4096

// ---------------------------------------------------------------------------
// fp16 pool (2-byte slots, element offsets)
// ---------------------------------------------------------------------------
#define SZ_ACT (4096ull * 1024ull)
#define SZ_W   (1024ull * 1024ull)
#define OFF_XQ_HI 0ull
#define OFF_XQ_LO (OFF_XQ_HI + SZ_ACT)
#define OFF_XK_HI (OFF_XQ_LO + SZ_ACT)
#define OFF_XK_LO (OFF_XK_HI + SZ_ACT)
#define OFF_XV_HI (OFF_XK_LO + SZ_ACT)
#define OFF_XV_LO (OFF_XV_HI + SZ_ACT)
#define OFF_WQ    (OFF_XV_LO + SZ_ACT)
#define OFF_WK    (OFF_WQ + SZ_W)
#define OFF_WV    (OFF_WK + SZ_W)
#define OFF_WO    (OFF_WV + SZ_W)
#define OFF_CTX_HI (OFF_WO + SZ_W)
#define OFF_CTX_LO (OFF_CTX_HI + SZ_ACT)
// head-major attention operands: [b*16+h][s][64]
#define OFF_AQ_HI (OFF_CTX_LO + SZ_ACT)
#define OFF_AQ_LO (OFF_AQ_HI + SZ_ACT)
#define OFF_AK    (OFF_AQ_LO + SZ_ACT)
#define OFF_AVF   (OFF_AK + SZ_ACT)
#define P_TOTAL   (OFF_AVF + SZ_ACT)
__device__ uint16_t g_pool[P_TOTAL];

// ---------------------------------------------------------------------------
// PTX helpers — baseline ISA only (cp.async / ldmatrix / mma.sync / cvt)
// ---------------------------------------------------------------------------
__device__ __forceinline__ uint32_t smem_u32(const void* p) {
    uint32_t a;
    asm("{ .reg .u64 t; cvta.to.shared.u64 t, %1; cvt.u32.u64 %0, t; }"
        : "=r"(a) : "l"(p));
    return a;
}

#define CP_ASYNC16(dst, src) \
    asm volatile("cp.async.cg.shared.global [%0], [%1], 16;" :: "r"(dst), "l"(src))
#define CP_COMMIT() asm volatile("cp.async.commit_group;" ::: "memory")
#define CP_WAIT(N)  asm volatile("cp.async.wait_group %0;" :: "n"(N) : "memory")

#define LDSM4(R, addr) \
    asm volatile("ldmatrix.sync.aligned.m8n8.x4.shared.b16 {%0,%1,%2,%3}, [%4];" \
        : "=r"((R)[0]), "=r"((R)[1]), "=r"((R)[2]), "=r"((R)[3]) : "r"(addr))
#define LDSM4T(R, addr) \
    asm volatile("ldmatrix.sync.aligned.m8n8.x4.trans.shared.b16 {%0,%1,%2,%3}, [%4];" \
        : "=r"((R)[0]), "=r"((R)[1]), "=r"((R)[2]), "=r"((R)[3]) : "r"(addr))

#define MMAF16(C, A, b0, b1) \
    asm volatile("mma.sync.aligned.m16n8k16.row.col.f32.f16.f16.f32 " \
        "{%0,%1,%2,%3}, {%4,%5,%6,%7}, {%8,%9}, {%0,%1,%2,%3};" \
        : "+f"((C)[0]), "+f"((C)[1]), "+f"((C)[2]), "+f"((C)[3]) \
        : "r"((A)[0]), "r"((A)[1]), "r"((A)[2]), "r"((A)[3]), "r"(b0), "r"(b1))

__device__ __forceinline__ float ex2(float x) {
    float r; asm("ex2.approx.ftz.f32 %0, %1;" : "=f"(r) : "f"(x)); return r;
}
__device__ __forceinline__ uint32_t packh(float lo, float hi) {
    __half2 h = __floats2half2_rn(lo, hi);
    return *reinterpret_cast<uint32_t*>(&h);
}
__device__ __forceinline__ void packh_split(float a, float b, uint32_t& hi, uint32_t& lo) {
    __half2 h = __floats2half2_rn(a, b);
    hi = *reinterpret_cast<uint32_t*>(&h);
    lo = packh(a - __low2float(h), b - __high2float(h));
}

// ---------------------------------------------------------------------------
// ONE merged fp32 -> fp16 conversion. x tensors: 2-term hi/lo. Weights: single.
// 8 elements/thread, 16B stores. Blocks of 2048 elements.
// ---------------------------------------------------------------------------
__global__ __launch_bounds__(256) void convert_all(
    const float* __restrict__ q, const float* __restrict__ k,
    const float* __restrict__ v, const float* __restrict__ wq,
    const float* __restrict__ wk, const float* __restrict__ wv,
    const float* __restrict__ wo)
{
    const int blk = blockIdx.x;
    if (blk < 6144) {
        int t = blk >> 11;
        const float* src = (t == 0) ? q : (t == 1) ? k : v;
        size_t hiOff = (t == 0) ? OFF_XQ_HI : (t == 1) ? OFF_XK_HI : OFF_XV_HI;
        size_t base = ((size_t)(blk & 2047)) << 11;
        size_t i = base + (size_t)threadIdx.x * 8;
        float4 x0 = *(const float4*)(src + i);
        float4 x1 = *(const float4*)(src + i + 4);
        float vv[8] = {x0.x, x0.y, x0.z, x0.w, x1.x, x1.y, x1.z, x1.w};
        uint32_t hp[4], lp[4];
#pragma unroll
        for (int p = 0; p < 4; p++)
            packh_split(vv[2 * p], vv[2 * p + 1], hp[p], lp[p]);
        *reinterpret_cast<uint4*>(g_pool + hiOff + i) = make_uint4(hp[0], hp[1], hp[2], hp[3]);
        *reinterpret_cast<uint4*>(g_pool + hiOff + SZ_ACT + i) = make_uint4(lp[0], lp[1], lp[2], lp[3]);
    } else {
        int b2 = blk - 6144;
        int t = b2 >> 9;
        const float* src = (t == 0) ? wq : (t == 1) ? wk : (t == 2) ? wv : wo;
        size_t off = OFF_WQ + (size_t)t * SZ_W;
        size_t base = ((size_t)(b2 & 511)) << 11;
        size_t i = base + (size_t)threadIdx.x * 8;
        float4 x0 = *(const float4*)(src + i);
        float4 x1 = *(const float4*)(src + i + 4);
        uint32_t hp[4];
        hp[0] = packh(x0.x, x0.y); hp[1] = packh(x0.z, x0.w);
        hp[2] = packh(x1.x, x1.y); hp[3] = packh(x1.z, x1.w);
        *reinterpret_cast<uint4*>(g_pool + off + i) = make_uint4(hp[0], hp[1], hp[2], hp[3]);
    }
}

// ---------------------------------------------------------------------------
// GEMM core (fp16 2-term): C = (Ahi+Alo) * B^T.  CTA tile 128x128, 256 thr,
// 2(M)x4(N) warps, warp tile 64x32. Tiles: Ahi | Alo | B  (8 KB each).
// 3-stage pipeline, single barrier per k-tile, 2 CTAs/SM.
// ---------------------------------------------------------------------------
#define NT 32
#define KT 32
#define TILEB 8192
#define STAGEB (3 * TILEB)        // 24576
#define GNSTG 3
#define GEMM_SMEM (GNSTG * STAGEB)  // 73728

__device__ __forceinline__ uint32_t gsw(int r, int c) {
    uint32_t line = (uint32_t)(r >> 1);
    uint32_t cil  = ((uint32_t)(r & 1) << 2) | (uint32_t)c;
    return (line << 7) + ((cil ^ (line & 7)) << 4);
}

struct GemmAcc { float a[4][4][4]; };

__device__ __forceinline__ void gemm_core(
    uint32_t sbase, size_t aHi, size_t aLo, size_t bOff,
    int m0, int n0, GemmAcc& A)
{
    const int tid  = threadIdx.x;
    const int lane = tid & 31;
    const int wid  = tid >> 5;

    const uint16_t* gp0 = g_pool + aHi + (size_t)m0 * 1024;
    const uint16_t* gp1 = g_pool + aLo + (size_t)m0 * 1024;
    const uint16_t* gp2 = g_pool + bOff + (size_t)n0 * 1024;

    auto issue = [&](int kt, int stage) {
        const int kc = kt * KT;
#pragma unroll
        for (int j = 0; j < 6; j++) {
            int c    = tid + j * 256;
            int tile = c >> 9;          // 0 Ahi, 1 Alo, 2 B
            int w    = c & 511;
            int r    = w >> 2;
            int qq   = w & 3;
            uint32_t dst = sbase + stage * STAGEB + tile * TILEB + gsw(r, qq);
            const uint16_t* base = (tile == 0) ? gp0 : (tile == 1) ? gp1 : gp2;
            CP_ASYNC16(dst, base + (size_t)r * 1024 + kc + qq * 8);
        }
        CP_COMMIT();
    };

    issue(0, 0);
    issue(1, 1);

    const int wm = wid & 1;
    const int wn = wid >> 1;
    const int a_row = (lane & 7) + ((lane >> 3) & 1) * 8;
    const int a_chk = (lane >> 4);
    const int b_row = (lane & 7) + ((lane >> 4)) * 8;
    const int b_chk = ((lane >> 3) & 1);

#pragma unroll
    for (int i = 0; i < 4; i++)
#pragma unroll
        for (int j = 0; j < 4; j++)
#pragma unroll
            for (int e = 0; e < 4; e++) A.a[i][j][e] = 0.f;

    int stg = 0;        // kt % 3
    int stg2 = 2;       // (kt+2) % 3
    for (int kt = 0; kt < NT; kt++) {
        if (kt < NT - 1) CP_WAIT(1); else CP_WAIT(0);
        __syncthreads();    // all warps done reading stage (kt-1)%3 == stg2

        if (kt + 2 < NT) issue(kt + 2, stg2);

        const uint32_t st = sbase + stg * STAGEB;

#pragma unroll
        for (int ks = 0; ks < 2; ks++) {
            uint32_t bF[2][4];
#pragma unroll
            for (int j = 0; j < 2; j++) {
                uint32_t bd = st + 2 * TILEB +
                              gsw(wn * 32 + j * 16 + b_row, ks * 2 + b_chk);
                LDSM4(bF[j], bd);
            }
#pragma unroll
            for (int ih = 0; ih < 2; ih++) {
                uint32_t aH[2][4], aL[2][4];
#pragma unroll
                for (int i = 0; i < 2; i++) {
                    uint32_t ad = st +
                        gsw(wm * 64 + (ih * 2 + i) * 16 + a_row, ks * 2 + a_chk);
                    LDSM4(aH[i], ad);
                    LDSM4(aL[i], ad + TILEB);
                }
#pragma unroll
                for (int i = 0; i < 2; i++) {
#pragma unroll
                    for (int jf = 0; jf < 4; jf++) {
                        uint32_t h0 = bF[jf >> 1][(jf & 1) * 2];
                        uint32_t h1 = bF[jf >> 1][(jf & 1) * 2 + 1];
                        float* acc = A.a[ih * 2 + i][jf];
                        MMAF16(acc, aH[i], h0, h1);
                        MMAF16(acc, aL[i], h0, h1);
                    }
                }
            }
        }
        stg  = (stg == 2) ? 0 : stg + 1;
        stg2 = (stg2 == 2) ? 0 : stg2 + 1;
    }
    __syncthreads();
}

// QKV projections merged: blockIdx.z 0=Q (fp16 2-term out), 1=K (single), 2=V (single)
__global__ __launch_bounds__(256, 2) void gemm_qkv(
    const float* __restrict__ bq, const float* __restrict__ bk,
    const float* __restrict__ bv)
{
    extern __shared__ char sm[];
    const uint32_t sbase = smem_u32(sm);
    const int lane = threadIdx.x & 31;
    const int wid  = threadIdx.x >> 5;
    const int m0 = blockIdx.y << 7;
    const int n0 = blockIdx.x << 7;
    const int z  = blockIdx.z;

    size_t aHi, bOff;
    const float* bias;
    if (z == 0) { aHi = OFF_XQ_HI; bOff = OFF_WQ; bias = bq; }
    else if (z == 1) { aHi = OFF_XK_HI; bOff = OFF_WK; bias = bk; }
    else { aHi = OFF_XV_HI; bOff = OFF_WV; bias = bv; }

    GemmAcc A;
    gemm_core(sbase, aHi, aHi + SZ_ACT, bOff, m0, n0, A);

    const int mrb = m0 + (wid & 1) * 64;
    const int ncb = n0 + (wid >> 1) * 32;
#pragma unroll
    for (int i = 0; i < 4; i++) {
        int r0 = mrb + i * 16 + (lane >> 2);
#pragma unroll
        for (int jf = 0; jf < 4; jf++) {
            int c = ncb + jf * 8 + (lane & 3) * 2;
            float bx = __ldg(bias + c);
            float by = __ldg(bias + c + 1);
            int h = c >> 6, d = c & 63;
            size_t ix0 = ((size_t)(((r0 >> 11) << 4) | h) << 17)
                       + ((size_t)(r0 & 2047) << 6) + d;
            size_t ix1 = ix0 + (8ull << 6);
            float v00 = A.a[i][jf][0] + bx, v01 = A.a[i][jf][1] + by;
            float v10 = A.a[i][jf][2] + bx, v11 = A.a[i][jf][3] + by;
            if (z == 0) {
                uint32_t h0, l0, h1, l1;
                packh_split(v00, v01, h0, l0);
                packh_split(v10, v11, h1, l1);
                *reinterpret_cast<uint32_t*>(g_pool + OFF_AQ_HI + ix0) = h0;
                *reinterpret_cast<uint32_t*>(g_pool + OFF_AQ_LO + ix0) = l0;
                *reinterpret_cast<uint32_t*>(g_pool + OFF_AQ_HI + ix1) = h1;
                *reinterpret_cast<uint32_t*>(g_pool + OFF_AQ_LO + ix1) = l1;
            } else {
                size_t o = (z == 1) ? OFF_AK : OFF_AVF;
                *reinterpret_cast<uint32_t*>(g_pool + o + ix0) = packh(v00, v01);
                *reinterpret_cast<uint32_t*>(g_pool + o + ix1) = packh(v10, v11);
            }
        }
    }
}

// Output projection: ctx (fp16 2-term) x Wo^T (single) + bo -> fp32 out
__global__ __launch_bounds__(256, 2) void gemm_out(
    const float* __restrict__ bias, float* __restrict__ ext)
{
    extern __shared__ char sm[];
    const uint32_t sbase = smem_u32(sm);
    const int lane = threadIdx.x & 31;
    const int wid  = threadIdx.x >> 5;
    const int m0 = blockIdx.y << 7;
    const int n0 = blockIdx.x << 7;

    GemmAcc A;
    gemm_core(sbase, OFF_CTX_HI, OFF_CTX_LO, OFF_WO, m0, n0, A);

    const int mrb = m0 + (wid & 1) * 64;
    const int ncb = n0 + (wid >> 1) * 32;
#pragma unroll
    for (int i = 0; i < 4; i++) {
        int r0 = mrb + i * 16 + (lane >> 2);
#pragma unroll
        for (int jf = 0; jf < 4; jf++) {
            int cb = ncb + jf * 8 + (lane & 3) * 2;
            float bx = __ldg(bias + cb);
            float by = __ldg(bias + cb + 1);
            float2 o0 = make_float2(A.a[i][jf][0] + bx, A.a[i][jf][1] + by);
            float2 o1 = make_float2(A.a[i][jf][2] + bx, A.a[i][jf][3] + by);
            *reinterpret_cast<float2*>(ext + (size_t)r0 * 1024 + cb)       = o0;
            *reinterpret_cast<float2*>(ext + (size_t)(r0 + 8) * 1024 + cb) = o1;
        }
    }
}

// ---------------------------------------------------------------------------
// Flash attention, all fp16: QK^T = Q(2-term) x K(single) (2 MMAs),
// PV = P x V single (1 MMA). Stage = K 8K | Vf 8K = 16 KB; 3 stages.
// CTA: 128 queries x one (b,h). 8 warps x 16-q tiles. Key tiles of 64.
// ---------------------------------------------------------------------------
#define ATT_STAGE 16384
#define ATT_NSTG  3
#define ATT_SMEM  (ATT_NSTG * ATT_STAGE)  // 49152

__global__ __launch_bounds__(256, 2) void attn_tc()
{
    extern __shared__ char sm[];
    const uint32_t sb = smem_u32(sm);
    const int tid = threadIdx.x, lane = tid & 31, wid = tid >> 5;
    const int bh = blockIdx.y;
    const int q0 = blockIdx.x << 7;

    const uint16_t* Qh = g_pool + OFF_AQ_HI + ((size_t)bh << 17) + ((size_t)q0 << 6);
    const uint16_t* Ql = g_pool + OFF_AQ_LO + ((size_t)bh << 17) + ((size_t)q0 << 6);
    const uint16_t* Kf = g_pool + OFF_AK  + ((size_t)bh << 17);
    const uint16_t* Vf = g_pool + OFF_AVF + ((size_t)bh << 17);

    // ---- stage Q tile (128x64 hi+lo) into smem, then to registers ----
#pragma unroll
    for (int j = 0; j < 8; j++) {
        int c = tid + j * 256;
        int t = c >> 10;
        int r = (c >> 3) & 127;
        int cb = c & 7;
        uint32_t dst = sb + t * 16384 + r * 128 + ((cb ^ (r & 7)) << 4);
        const uint16_t* src = (t ? Ql : Qh) + (size_t)r * 64 + cb * 8;
        CP_ASYNC16(dst, src);
    }
    CP_COMMIT(); CP_WAIT(0);
    __syncthreads();

    uint32_t aQh[4][4], aQl[4][4];
    {
        int row = (wid << 4) + (lane & 7) + ((lane >> 3) & 1) * 8;
#pragma unroll
        for (int ks = 0; ks < 4; ks++) {
            int cb = ks * 2 + (lane >> 4);
            uint32_t ad = sb + row * 128 + ((cb ^ (row & 7)) << 4);
            LDSM4(aQh[ks], ad);
            LDSM4(aQl[ks], ad + 16384);
        }
    }
    __syncthreads();

    // ---- KV pipeline: stage = K | Vf, 1024 chunks -> 4 per thread ----
    auto issue = [&](int kt, int stg) {
        const int k0 = kt << 6;
#pragma unroll
        for (int j = 0; j < 4; j++) {
            int c = tid + j * 256;
            int t = c >> 9;              // 0 K, 1 Vf
            int r = (c >> 3) & 63;
            int cb = c & 7;
            uint32_t dst = sb + stg * ATT_STAGE + t * 8192 + r * 128 + ((cb ^ (r & 7)) << 4);
            const uint16_t* base = (t == 0) ? Kf : Vf;
            CP_ASYNC16(dst, base + (size_t)(k0 + r) * 64 + cb * 8);
        }
        CP_COMMIT();
    };
    issue(0, 0);
    issue(1, 1);
    issue(2, 2);

    float O[8][4];
#pragma unroll
    for (int f = 0; f < 8; f++)
#pragma unroll
        for (int e = 0; e < 4; e++) O[f][e] = 0.f;
    float l0 = 0.f, l1 = 0.f;
    const float cs = 0.125f * 1.4426950408889634f;

    const int krow = (lane & 7) + (lane >> 4) * 8;
    const int kcb  = (lane >> 3) & 1;
    const int vrow = (lane & 7) + ((lane >> 3) & 1) * 8;
    const int vcb  = lane >> 4;

    int stg = 0;  // kt % 3
    for (int kt = 0; kt < 32; kt++) {
        if (kt < 30) CP_WAIT(2);
        else if (kt == 30) CP_WAIT(1);
        else CP_WAIT(0);
        __syncthreads();
        const uint32_t st = sb + stg * ATT_STAGE;

        // two key-halves of 32 keys each: compute S-half, softmax, PV-half
#pragma unroll
        for (int h2 = 0; h2 < 2; h2++) {
            float S[4][4];
#pragma unroll
            for (int f = 0; f < 4; f++)
#pragma unroll
                for (int e = 0; e < 4; e++) S[f][e] = 0.f;

            // S = Q K^T: Qhi*K + Qlo*K (fp16)
#pragma unroll
            for (int ks = 0; ks < 4; ks++) {
#pragma unroll
                for (int gg = 0; gg < 2; gg++) {
                    int g = 2 * h2 + gg;
                    int rr = g * 16 + krow;
                    int cb = ks * 2 + kcb;
                    uint32_t ad = st + rr * 128 + ((cb ^ (rr & 7)) << 4);
                    uint32_t KF[4];
                    LDSM4(KF, ad);
                    MMAF16(S[2 * gg],     aQh[ks], KF[0], KF[1]);
                    MMAF16(S[2 * gg],     aQl[ks], KF[0], KF[1]);
                    MMAF16(S[2 * gg + 1], aQh[ks], KF[2], KF[3]);
                    MMAF16(S[2 * gg + 1], aQl[ks], KF[2], KF[3]);
                }
            }

#pragma unroll
            for (int f = 0; f < 4; f++) {
#pragma unroll
                for (int e = 0; e < 4; e++) S[f][e] = ex2(S[f][e] * cs);
                l0 += S[f][0] + S[f][1];
                l1 += S[f][2] + S[f][3];
            }

            // O += P V, fp16 single term
#pragma unroll
            for (int jj = 0; jj < 2; jj++) {
                int kk = 2 * h2 + jj;
                uint32_t pF[4];
                float* Sa = S[2 * jj];
                float* Sb = S[2 * jj + 1];
                pF[0] = packh(Sa[0], Sa[1]);
                pF[1] = packh(Sa[2], Sa[3]);
                pF[2] = packh(Sb[0], Sb[1]);
                pF[3] = packh(Sb[2], Sb[3]);
#pragma unroll
                for (int dp = 0; dp < 4; dp++) {
                    int rr = kk * 16 + vrow;
                    int cb = dp * 2 + vcb;
                    uint32_t ad = st + 8192 + rr * 128 + ((cb ^ (rr & 7)) << 4);
                    uint32_t VF[4];
                    LDSM4T(VF, ad);
                    MMAF16(O[2 * dp],     pF, VF[0], VF[1]);
                    MMAF16(O[2 * dp + 1], pF, VF[2], VF[3]);
                }
            }
        }

        __syncthreads();
        if (kt + 3 < 32) issue(kt + 3, stg);   // tile kt+3 reuses stage kt%3
        stg = (stg == 2) ? 0 : stg + 1;
    }

    // ---- epilogue: normalize and write ctx as fp16 hi/lo [b,s,1024] ----
    l0 += __shfl_xor_sync(0xffffffffu, l0, 1);
    l0 += __shfl_xor_sync(0xffffffffu, l0, 2);
    l1 += __shfl_xor_sync(0xffffffffu, l1, 1);
    l1 += __shfl_xor_sync(0xffffffffu, l1, 2);
    const float inv0 = 1.f / l0;
    const float inv1 = 1.f / l1;

    const int b = bh >> 4, h = bh & 15;
    const int r0g = b * 2048 + q0 + (wid << 4) + (lane >> 2);
#pragma unroll
    for (int f = 0; f < 8; f++) {
        int col = (h << 6) + f * 8 + (lane & 3) * 2;
        uint32_t h0, l0u, h1, l1u;
        packh_split(O[f][0] * inv0, O[f][1] * inv0, h0, l0u);
        packh_split(O[f][2] * inv1, O[f][3] * inv1, h1, l1u);
        size_t i0 = (size_t)r0g * 1024 + col;
        size_t i1 = (size_t)(r0g + 8) * 1024 + col;
        *reinterpret_cast<uint32_t*>(g_pool + OFF_CTX_HI + i0) = h0;
        *reinterpret_cast<uint32_t*>(g_pool + OFF_CTX_LO + i0) = l0u;
        *reinterpret_cast<uint32_t*>(g_pool + OFF_CTX_HI + i1) = h1;
        *reinterpret_cast<uint32_t*>(g_pool + OFF_CTX_LO + i1) = l1u;
    }
}

// ---------------------------------------------------------------------------
extern "C" void kernel_launch(void* const* d_in, const int* in_sizes, int n_in,
                              void* d_out, int out_size)
{
    const float* query = (const float*)d_in[0];
    const float* key   = (const float*)d_in[1];
    const float* value = (const float*)d_in[2];
    const float* Wq = (const float*)d_in[3];
    const float* bq = (const float*)d_in[4];
    const float* Wk = (const float*)d_in[5];
    const float* bk = (const float*)d_in[6];
    const float* Wv = (const float*)d_in[7];
    const float* bv = (const float*)d_in[8];
    const float* Wo = (const float*)d_in[9];
    const float* bo = (const float*)d_in[10];
    float* out = (float*)d_out;

    cudaFuncSetAttribute(gemm_qkv, cudaFuncAttributeMaxDynamicSharedMemorySize, GEMM_SMEM);
    cudaFuncSetAttribute(gemm_out, cudaFuncAttributeMaxDynamicSharedMemorySize, GEMM_SMEM);
    cudaFuncSetAttribute(attn_tc,  cudaFuncAttributeMaxDynamicSharedMemorySize, ATT_SMEM);

    convert_all<<<8192, 256>>>(query, key, value, Wq, Wk, Wv, Wo);

    gemm_qkv<<<dim3(DM / 128, MROWS / 128, 3), 256, GEMM_SMEM>>>(bq, bk, bv);

    attn_tc<<<dim3(SEQ / 128, BATCH * NH), 256, ATT_SMEM>>>();

    gemm_out<<<dim3(DM / 128, MROWS / 128), 256, GEMM_SMEM>>>(bo, out);
}